// round 2
// baseline (speedup 1.0000x reference)
#include <cuda_runtime.h>
#include <math.h>

#define B_SZ 4
#define LSEQ 512
#define DM   1024
#define ED   2048
#define NS   16
#define DTR  64
#define KX   96                 // DTR + 2*NS
#define MROWS (B_SZ*LSEQ)       // 2048
#define SPLITS 8

// ---------------- scratch (static device globals; no runtime allocation) ----
__device__ __align__(16) float g_xz   [(size_t)MROWS * 2 * ED];   // 32 MB
__device__ __align__(16) float g_xconv[(size_t)MROWS * ED];       // 16 MB
__device__ __align__(16) float g_dbc  [(size_t)MROWS * KX];
__device__ __align__(16) float g_dbcp [(size_t)SPLITS * MROWS * KX];
__device__ __align__(16) float g_delta[(size_t)MROWS * ED];       // 16 MB
__device__ __align__(16) float g_y    [(size_t)MROWS * ED];       // 16 MB

__device__ __forceinline__ float sigmoidf_(float v) {
    return 1.f / (1.f + __expf(-v));
}

// ---------------------------------------------------------------------------
// Generic NT SGEMM: C[m,n] = sum_k A[m,k] * B[n,k]
// BM=BN=128, BK=8, 8x8 per thread, 256 threads.
// Requirements: M % 128 == 0, K % 8 == 0, lda/ldb % 4 == 0. N is guarded.
// blockIdx.z = K-split index (partials written at C + z*M*ldc).
// epi: 0 = none, 1 = softplus(v + bias[n])
// ---------------------------------------------------------------------------
__global__ __launch_bounds__(256) void sgemm_nt(
    const float* __restrict__ A, int lda,
    const float* __restrict__ Bw, int ldb,
    float* __restrict__ C, int ldc,
    int M, int N, int Ktot, int ksz,
    int epi, const float* __restrict__ bias)
{
    __shared__ float As[8][128];
    __shared__ float Bs[8][128];

    const int bm = blockIdx.y * 128;
    const int bn = blockIdx.x * 128;
    const int s  = blockIdx.z;
    const int k0 = s * ksz;
    int k1 = k0 + ksz; if (k1 > Ktot) k1 = Ktot;
    float* Cout = C + (size_t)s * (size_t)M * (size_t)ldc;

    const int tid  = threadIdx.x;
    const int lrow = tid >> 1;          // 0..127
    const int lcol = (tid & 1) * 4;     // 0 or 4
    const int tm   = (tid >> 4) * 8;    // 0..120
    const int tn   = (tid & 15) * 8;    // 0..120

    const float* Aptr = A + (size_t)(bm + lrow) * lda + lcol;
    const bool   bval = (bn + lrow) < N;
    const float* Bptr = Bw + (size_t)(bn + lrow) * ldb + lcol;

    float acc[8][8];
#pragma unroll
    for (int i = 0; i < 8; i++)
#pragma unroll
        for (int j = 0; j < 8; j++) acc[i][j] = 0.f;

    for (int k = k0; k < k1; k += 8) {
        float4 av = *reinterpret_cast<const float4*>(Aptr + k);
        float4 bv = bval ? *reinterpret_cast<const float4*>(Bptr + k)
                         : make_float4(0.f, 0.f, 0.f, 0.f);
        As[lcol + 0][lrow] = av.x; As[lcol + 1][lrow] = av.y;
        As[lcol + 2][lrow] = av.z; As[lcol + 3][lrow] = av.w;
        Bs[lcol + 0][lrow] = bv.x; Bs[lcol + 1][lrow] = bv.y;
        Bs[lcol + 2][lrow] = bv.z; Bs[lcol + 3][lrow] = bv.w;
        __syncthreads();

#pragma unroll
        for (int kk = 0; kk < 8; kk++) {
            float4 a0 = *reinterpret_cast<const float4*>(&As[kk][tm]);
            float4 a1 = *reinterpret_cast<const float4*>(&As[kk][tm + 4]);
            float4 b0 = *reinterpret_cast<const float4*>(&Bs[kk][tn]);
            float4 b1 = *reinterpret_cast<const float4*>(&Bs[kk][tn + 4]);
            float ar[8] = {a0.x, a0.y, a0.z, a0.w, a1.x, a1.y, a1.z, a1.w};
            float br[8] = {b0.x, b0.y, b0.z, b0.w, b1.x, b1.y, b1.z, b1.w};
#pragma unroll
            for (int i = 0; i < 8; i++)
#pragma unroll
                for (int j = 0; j < 8; j++)
                    acc[i][j] = fmaf(ar[i], br[j], acc[i][j]);
        }
        __syncthreads();
    }

#pragma unroll
    for (int i = 0; i < 8; i++) {
        size_t row = (size_t)(bm + tm + i) * (size_t)ldc;
#pragma unroll
        for (int j = 0; j < 8; j++) {
            int n = bn + tn + j;
            if (n < N) {
                float v = acc[i][j];
                if (epi == 1) {
                    v += bias[n];
                    v = (v > 20.f) ? v : log1pf(__expf(v));   // softplus
                }
                Cout[row + n] = v;
            }
        }
    }
}

// ---------------------------------------------------------------------------
// Reduce split-K partials: out[i] = sum_s part[s*n + i]
// ---------------------------------------------------------------------------
__global__ void reduce_splits(const float* __restrict__ part,
                              float* __restrict__ outp, int n)
{
    int i = blockIdx.x * blockDim.x + threadIdx.x;
    if (i < n) {
        float s = 0.f;
#pragma unroll
        for (int j = 0; j < SPLITS; j++) s += part[(size_t)j * n + i];
        outp[i] = s;
    }
}

// ---------------------------------------------------------------------------
// Causal depthwise conv (K=4) + SiLU.
// Input: first ED columns of g_xz row (b, tt) where tt is time-reversed for
// the backward branch. Output xconv[b, t, e] in branch-local time order.
// ---------------------------------------------------------------------------
__global__ __launch_bounds__(256) void conv_silu_kernel(
    const float* __restrict__ xz,
    const float* __restrict__ w,      // (ED, 1, 4)
    const float* __restrict__ bconv,  // (ED,)
    float* __restrict__ xc, int rev)
{
    int idx = blockIdx.x * blockDim.x + threadIdx.x;
    if (idx >= MROWS * ED) return;
    int e = idx % ED;
    int t = (idx / ED) % LSEQ;
    int b = idx / (ED * LSEQ);

    float acc = bconv[e];
#pragma unroll
    for (int i = 0; i < 4; i++) {
        int tau = t - 3 + i;
        if (tau >= 0) {
            int tt = rev ? (LSEQ - 1 - tau) : tau;
            acc = fmaf(w[e * 4 + i],
                       xz[((size_t)b * LSEQ + tt) * (2 * ED) + e], acc);
        }
    }
    xc[idx] = acc * sigmoidf_(acc);   // SiLU
}

// ---------------------------------------------------------------------------
// Selective scan. 4 states per thread, 4 lanes per channel (N=16), butterfly
// shfl reduction over the 4-lane group. Block = 128 threads = 32 channels.
// Grid = B * ED/32 = 256 blocks -> 1024 warps chip-wide.
// rev=0: y[b,t,e] = val
// rev=1: y[b,L-1-t,e] = 0.5*(y[b,L-1-t,e] + val)   (final combine)
// ---------------------------------------------------------------------------
__global__ __launch_bounds__(128) void scan_kernel(
    const float* __restrict__ delta,   // (MROWS, ED) branch time order
    const float* __restrict__ xconv,   // (MROWS, ED)
    const float* __restrict__ dbc,     // (MROWS, 96): [.,64:80]=B, [.,80:96]=C
    const float* __restrict__ xz,      // (MROWS, 2*ED) original time order
    const float* __restrict__ A_log,   // (ED, 16)
    const float* __restrict__ Dp,      // (ED,)
    float* __restrict__ y, int rev)
{
    const int b  = blockIdx.x >> 6;          // ED/32 = 64 blocks per batch
    const int ec = blockIdx.x & 63;
    const int tid = threadIdx.x;
    const int e = ec * 32 + (tid >> 2);      // channel
    const int g = tid & 3;                   // state-group (4 states each)

    float4 al = *reinterpret_cast<const float4*>(&A_log[e * NS + g * 4]);
    const float A0 = -__expf(al.x), A1 = -__expf(al.y),
                A2 = -__expf(al.z), A3 = -__expf(al.w);
    const float dp = Dp[e];

    float h0 = 0.f, h1 = 0.f, h2 = 0.f, h3 = 0.f;
    const size_t baseBL = (size_t)b * LSEQ;

    for (int t = 0; t < LSEQ; t++) {
        const size_t row = baseBL + t;
        const float d  = delta[row * ED + e];
        const float xv = xconv[row * ED + e];
        const int   tt = rev ? (LSEQ - 1 - t) : t;
        const float zv = xz[(baseBL + tt) * (2 * ED) + ED + e];
        float4 Bv = *reinterpret_cast<const float4*>(&dbc[row * KX + DTR + g * 4]);
        float4 Cv = *reinterpret_cast<const float4*>(&dbc[row * KX + DTR + NS + g * 4]);

        const float dx = d * xv;
        h0 = fmaf(__expf(d * A0), h0, dx * Bv.x);
        h1 = fmaf(__expf(d * A1), h1, dx * Bv.y);
        h2 = fmaf(__expf(d * A2), h2, dx * Bv.z);
        h3 = fmaf(__expf(d * A3), h3, dx * Bv.w);

        float yp = h0 * Cv.x + h1 * Cv.y + h2 * Cv.z + h3 * Cv.w;
        yp += __shfl_xor_sync(0xffffffffu, yp, 1);
        yp += __shfl_xor_sync(0xffffffffu, yp, 2);

        if (g == 0) {
            float yt  = yp + dp * xv;
            float val = yt * (zv * sigmoidf_(zv));
            size_t orow = rev ? (baseBL + (LSEQ - 1 - t)) : row;
            size_t oi = orow * ED + e;
            if (rev) y[oi] = 0.5f * (y[oi] + val);
            else     y[oi] = val;
        }
    }
}

// ---------------------------------------------------------------------------
extern "C" void kernel_launch(void* const* d_in, const int* in_sizes, int n_in,
                              void* d_out, int out_size)
{
    (void)in_sizes; (void)n_in; (void)out_size;
    const float* x     = (const float*)d_in[0];
    const float* W_in  = (const float*)d_in[1];
    const float* W_out = (const float*)d_in[16];
    float* out = (float*)d_out;

    float *p_xz, *p_xc, *p_dbc, *p_dbcp, *p_delta, *p_y;
    cudaGetSymbolAddress((void**)&p_xz,    g_xz);
    cudaGetSymbolAddress((void**)&p_xc,    g_xconv);
    cudaGetSymbolAddress((void**)&p_dbc,   g_dbc);
    cudaGetSymbolAddress((void**)&p_dbcp,  g_dbcp);
    cudaGetSymbolAddress((void**)&p_delta, g_delta);
    cudaGetSymbolAddress((void**)&p_y,     g_y);

    // 1) xz = x @ W_in.T : (2048 x 4096), K=1024
    sgemm_nt<<<dim3(2 * ED / 128, MROWS / 128, 1), 256>>>(
        x, DM, W_in, DM, p_xz, 2 * ED, MROWS, 2 * ED, DM, DM, 0, nullptr);

    for (int dir = 0; dir < 2; dir++) {
        const float* cw   = (const float*)d_in[dir ? 9  : 2];
        const float* cb   = (const float*)d_in[dir ? 10 : 3];
        const float* Wx   = (const float*)d_in[dir ? 11 : 4];
        const float* Wdt  = (const float*)d_in[dir ? 12 : 5];
        const float* bdt  = (const float*)d_in[dir ? 13 : 6];
        const float* Alog = (const float*)d_in[dir ? 14 : 7];
        const float* Dpv  = (const float*)d_in[dir ? 15 : 8];

        // 2) conv + silu
        conv_silu_kernel<<<(MROWS * ED) / 256, 256>>>(p_xz, cw, cb, p_xc, dir);

        // 3) dbc = xconv @ Wx.T : (2048 x 96), K=2048, split-K x8
        sgemm_nt<<<dim3(1, MROWS / 128, SPLITS), 256>>>(
            p_xc, ED, Wx, ED, p_dbcp, KX, MROWS, KX, ED, ED / SPLITS, 0, nullptr);
        reduce_splits<<<(MROWS * KX + 255) / 256, 256>>>(p_dbcp, p_dbc, MROWS * KX);

        // 4) delta = softplus(dbc[:, :64] @ Wdt.T + b_dt) : (2048 x 2048), K=64
        sgemm_nt<<<dim3(ED / 128, MROWS / 128, 1), 256>>>(
            p_dbc, KX, Wdt, DTR, p_delta, ED, MROWS, ED, DTR, DTR, 1, bdt);

        // 5) selective scan (+ gate, + combine for bwd branch)
        scan_kernel<<<B_SZ * (ED / 32), 128>>>(
            p_delta, p_xc, p_dbc, p_xz, Alog, Dpv, p_y, dir);
    }

    // 6) out = ycomb @ W_out.T : (2048 x 1024), K=2048
    sgemm_nt<<<dim3(DM / 128, MROWS / 128, 1), 256>>>(
        p_y, ED, W_out, ED, out, DM, MROWS, DM, ED, ED, 0, nullptr);
}

// round 4
// speedup vs baseline: 1.1517x; 1.1517x over previous
#include <cuda_runtime.h>
#include <math.h>

#define B_SZ 4
#define LSEQ 512
#define DM   1024
#define ED   2048
#define NS   16
#define DTR  64
#define KX   96                 // DTR + 2*NS
#define MROWS (B_SZ*LSEQ)       // 2048
#define SPLITS 8

// ---------------- scratch (static device globals; no runtime allocation) ----
__device__ __align__(16) float g_xz   [(size_t)MROWS * 2 * ED];   // 32 MB
__device__ __align__(16) float g_xconv[(size_t)MROWS * ED];       // 16 MB
__device__ __align__(16) float g_dbc  [(size_t)MROWS * KX];
__device__ __align__(16) float g_dbcp [(size_t)SPLITS * MROWS * KX];
__device__ __align__(16) float g_delta[(size_t)MROWS * ED];       // 16 MB
__device__ __align__(16) float g_y    [(size_t)MROWS * ED];       // 16 MB

__device__ __forceinline__ float sigmoidf_(float v) {
    return 1.f / (1.f + __expf(-v));
}

// ---------------------------------------------------------------------------
// tf32 warp MMA m16n8k8 (row.col): D = A*B + C  (C in-place)
// ---------------------------------------------------------------------------
__device__ __forceinline__ void mma_tf32(float c[4],
                                         unsigned a0, unsigned a1,
                                         unsigned a2, unsigned a3,
                                         unsigned b0, unsigned b1)
{
    asm volatile(
        "mma.sync.aligned.m16n8k8.row.col.f32.tf32.tf32.f32 "
        "{%0,%1,%2,%3}, {%4,%5,%6,%7}, {%8,%9}, {%0,%1,%2,%3};\n"
        : "+f"(c[0]), "+f"(c[1]), "+f"(c[2]), "+f"(c[3])
        : "r"(a0), "r"(a1), "r"(a2), "r"(a3), "r"(b0), "r"(b1));
}

__device__ __forceinline__ void split_tf32(float v, float& hi, float& lo)
{
    unsigned u;
    asm("cvt.rna.tf32.f32 %0, %1;" : "=r"(u) : "f"(v));
    hi = __uint_as_float(u);
    lo = v - hi;
}

// ---------------------------------------------------------------------------
// Tensor-core NT GEMM (compensated tf32, 3-MMA): C[m,n] = sum_k A[m,k]*B[n,k]
// BM=BN=128, BK=16, 256 threads = 8 warps (2x4), warp tile 64x32.
// M % 128 == 0, K % 16 == 0, lda/ldb % 4 == 0. N guarded.
// blockIdx.z = K-split (partials at C + z*M*ldc). epi1 = softplus(v+bias[n]).
// ---------------------------------------------------------------------------
__global__ __launch_bounds__(256) void tgemm_nt(
    const float* __restrict__ A, int lda,
    const float* __restrict__ Bw, int ldb,
    float* __restrict__ C, int ldc,
    int M, int N, int Ktot, int ksz,
    int epi, const float* __restrict__ bias)
{
    __shared__ float Ah[16][136], Al[16][136];
    __shared__ float Bh[16][136], Bl[16][136];

    const int bm = blockIdx.y * 128;
    const int bn = blockIdx.x * 128;
    const int s  = blockIdx.z;
    const int k0 = s * ksz;
    int k1 = k0 + ksz; if (k1 > Ktot) k1 = Ktot;
    float* Cout = C + (size_t)s * (size_t)M * (size_t)ldc;

    const int tid  = threadIdx.x;
    const int warp = tid >> 5, lane = tid & 31;
    const int wm = (warp >> 2) * 64;       // warp m-base within tile
    const int wn = (warp & 3) * 32;        // warp n-base within tile
    const int qr = lane >> 2;              // 0..7
    const int qc = lane & 3;               // 0..3

    // global staging: each thread owns rows (tid>>2) and (tid>>2)+64, col group tid&3
    const int gr = tid >> 2;               // 0..63
    const int gc = (tid & 3) * 4;          // 0,4,8,12
    const bool bval0 = (bn + gr)      < N;
    const bool bval1 = (bn + gr + 64) < N;
    const float* Ap0 = A  + (size_t)(bm + gr)      * lda + gc;
    const float* Ap1 = A  + (size_t)(bm + gr + 64) * lda + gc;
    const float* Bp0 = Bw + (size_t)(bn + gr)      * ldb + gc;
    const float* Bp1 = Bw + (size_t)(bn + gr + 64) * ldb + gc;

    float acc[4][4][4];
#pragma unroll
    for (int i = 0; i < 4; i++)
#pragma unroll
        for (int j = 0; j < 4; j++)
#pragma unroll
            for (int r = 0; r < 4; r++) acc[i][j][r] = 0.f;

    float4 av0, av1, bv0, bv1;
    const float4 z4 = make_float4(0.f, 0.f, 0.f, 0.f);

    // prologue load
    av0 = *reinterpret_cast<const float4*>(Ap0 + k0);
    av1 = *reinterpret_cast<const float4*>(Ap1 + k0);
    bv0 = bval0 ? *reinterpret_cast<const float4*>(Bp0 + k0) : z4;
    bv1 = bval1 ? *reinterpret_cast<const float4*>(Bp1 + k0) : z4;

    for (int k = k0; k < k1; k += 16) {
        // store staged regs to smem with hi/lo split
        {
            const float a0v[4] = {av0.x, av0.y, av0.z, av0.w};
            const float a1v[4] = {av1.x, av1.y, av1.z, av1.w};
            const float b0v[4] = {bv0.x, bv0.y, bv0.z, bv0.w};
            const float b1v[4] = {bv1.x, bv1.y, bv1.z, bv1.w};
#pragma unroll
            for (int j = 0; j < 4; j++) {
                float h, l;
                split_tf32(a0v[j], h, l); Ah[gc + j][gr]      = h; Al[gc + j][gr]      = l;
                split_tf32(a1v[j], h, l); Ah[gc + j][gr + 64] = h; Al[gc + j][gr + 64] = l;
                split_tf32(b0v[j], h, l); Bh[gc + j][gr]      = h; Bl[gc + j][gr]      = l;
                split_tf32(b1v[j], h, l); Bh[gc + j][gr + 64] = h; Bl[gc + j][gr + 64] = l;
            }
        }
        __syncthreads();

        // prefetch next k-tile while computing
        if (k + 16 < k1) {
            av0 = *reinterpret_cast<const float4*>(Ap0 + k + 16);
            av1 = *reinterpret_cast<const float4*>(Ap1 + k + 16);
            bv0 = bval0 ? *reinterpret_cast<const float4*>(Bp0 + k + 16) : z4;
            bv1 = bval1 ? *reinterpret_cast<const float4*>(Bp1 + k + 16) : z4;
        }

#pragma unroll
        for (int kk = 0; kk < 16; kk += 8) {
            // B fragments for 4 n-tiles
            unsigned bfh[4][2], bfl[4][2];
#pragma unroll
            for (int j = 0; j < 4; j++) {
                const int n0 = wn + j * 8;
                bfh[j][0] = __float_as_uint(Bh[kk + qc][n0 + qr]);
                bfh[j][1] = __float_as_uint(Bh[kk + qc + 4][n0 + qr]);
                bfl[j][0] = __float_as_uint(Bl[kk + qc][n0 + qr]);
                bfl[j][1] = __float_as_uint(Bl[kk + qc + 4][n0 + qr]);
            }
#pragma unroll
            for (int i = 0; i < 4; i++) {
                const int m0 = wm + i * 16;
                unsigned ah0 = __float_as_uint(Ah[kk + qc][m0 + qr]);
                unsigned ah1 = __float_as_uint(Ah[kk + qc][m0 + qr + 8]);
                unsigned ah2 = __float_as_uint(Ah[kk + qc + 4][m0 + qr]);
                unsigned ah3 = __float_as_uint(Ah[kk + qc + 4][m0 + qr + 8]);
                unsigned al0 = __float_as_uint(Al[kk + qc][m0 + qr]);
                unsigned al1 = __float_as_uint(Al[kk + qc][m0 + qr + 8]);
                unsigned al2 = __float_as_uint(Al[kk + qc + 4][m0 + qr]);
                unsigned al3 = __float_as_uint(Al[kk + qc + 4][m0 + qr + 8]);
#pragma unroll
                for (int j = 0; j < 4; j++) {
                    mma_tf32(acc[i][j], ah0, ah1, ah2, ah3, bfh[j][0], bfh[j][1]);
                    mma_tf32(acc[i][j], al0, al1, al2, al3, bfh[j][0], bfh[j][1]);
                    mma_tf32(acc[i][j], ah0, ah1, ah2, ah3, bfl[j][0], bfl[j][1]);
                }
            }
        }
        __syncthreads();
    }

    // epilogue: c0:(qr, 2qc) c1:(qr, 2qc+1) c2:(qr+8, 2qc) c3:(qr+8, 2qc+1)
#pragma unroll
    for (int i = 0; i < 4; i++) {
        const int row0 = bm + wm + i * 16 + qr;
#pragma unroll
        for (int j = 0; j < 4; j++) {
            const int col0 = bn + wn + j * 8 + qc * 2;
#pragma unroll
            for (int r = 0; r < 4; r++) {
                const int rr = row0 + (r >> 1) * 8;
                const int cc = col0 + (r & 1);
                if (cc < N) {
                    float v = acc[i][j][r];
                    if (epi == 1) {
                        v += bias[cc];
                        v = (v > 20.f) ? v : log1pf(__expf(v));
                    }
                    Cout[(size_t)rr * ldc + cc] = v;
                }
            }
        }
    }
}

// ---------------------------------------------------------------------------
// Reduce split-K partials: out[i] = sum_s part[s*n + i]
// ---------------------------------------------------------------------------
__global__ void reduce_splits(const float* __restrict__ part,
                              float* __restrict__ outp, int n)
{
    int i = blockIdx.x * blockDim.x + threadIdx.x;
    if (i < n) {
        float s = 0.f;
#pragma unroll
        for (int j = 0; j < SPLITS; j++) s += part[(size_t)j * n + i];
        outp[i] = s;
    }
}

// ---------------------------------------------------------------------------
// Causal depthwise conv (K=4) + SiLU.
// ---------------------------------------------------------------------------
__global__ __launch_bounds__(256) void conv_silu_kernel(
    const float* __restrict__ xz,
    const float* __restrict__ w,      // (ED, 1, 4)
    const float* __restrict__ bconv,  // (ED,)
    float* __restrict__ xc, int rev)
{
    int idx = blockIdx.x * blockDim.x + threadIdx.x;
    if (idx >= MROWS * ED) return;
    int e = idx % ED;
    int t = (idx / ED) % LSEQ;
    int b = idx / (ED * LSEQ);

    float acc = bconv[e];
#pragma unroll
    for (int i = 0; i < 4; i++) {
        int tau = t - 3 + i;
        if (tau >= 0) {
            int tt = rev ? (LSEQ - 1 - tau) : tau;
            acc = fmaf(w[e * 4 + i],
                       xz[((size_t)b * LSEQ + tt) * (2 * ED) + e], acc);
        }
    }
    xc[idx] = acc * sigmoidf_(acc);   // SiLU
}

// ---------------------------------------------------------------------------
// Selective scan. 4 states/thread, 4 lanes/channel, shfl reduce over group.
// ---------------------------------------------------------------------------
__global__ __launch_bounds__(128) void scan_kernel(
    const float* __restrict__ delta,   // (MROWS, ED) branch time order
    const float* __restrict__ xconv,   // (MROWS, ED)
    const float* __restrict__ dbc,     // (MROWS, 96)
    const float* __restrict__ xz,      // (MROWS, 2*ED) original time order
    const float* __restrict__ A_log,   // (ED, 16)
    const float* __restrict__ Dp,      // (ED,)
    float* __restrict__ y, int rev)
{
    const int b  = blockIdx.x >> 6;
    const int ec = blockIdx.x & 63;
    const int tid = threadIdx.x;
    const int e = ec * 32 + (tid >> 2);
    const int g = tid & 3;

    float4 al = *reinterpret_cast<const float4*>(&A_log[e * NS + g * 4]);
    const float A0 = -__expf(al.x), A1 = -__expf(al.y),
                A2 = -__expf(al.z), A3 = -__expf(al.w);
    const float dp = Dp[e];

    float h0 = 0.f, h1 = 0.f, h2 = 0.f, h3 = 0.f;
    const size_t baseBL = (size_t)b * LSEQ;

    for (int t = 0; t < LSEQ; t++) {
        const size_t row = baseBL + t;
        const float d  = delta[row * ED + e];
        const float xv = xconv[row * ED + e];
        const int   tt = rev ? (LSEQ - 1 - t) : t;
        const float zv = xz[(baseBL + tt) * (2 * ED) + ED + e];
        float4 Bv = *reinterpret_cast<const float4*>(&dbc[row * KX + DTR + g * 4]);
        float4 Cv = *reinterpret_cast<const float4*>(&dbc[row * KX + DTR + NS + g * 4]);

        const float dx = d * xv;
        h0 = fmaf(__expf(d * A0), h0, dx * Bv.x);
        h1 = fmaf(__expf(d * A1), h1, dx * Bv.y);
        h2 = fmaf(__expf(d * A2), h2, dx * Bv.z);
        h3 = fmaf(__expf(d * A3), h3, dx * Bv.w);

        float yp = h0 * Cv.x + h1 * Cv.y + h2 * Cv.z + h3 * Cv.w;
        yp += __shfl_xor_sync(0xffffffffu, yp, 1);
        yp += __shfl_xor_sync(0xffffffffu, yp, 2);

        if (g == 0) {
            float yt  = yp + dp * xv;
            float val = yt * (zv * sigmoidf_(zv));
            size_t orow = rev ? (baseBL + (LSEQ - 1 - t)) : row;
            size_t oi = orow * ED + e;
            if (rev) y[oi] = 0.5f * (y[oi] + val);
            else     y[oi] = val;
        }
    }
}

// ---------------------------------------------------------------------------
extern "C" void kernel_launch(void* const* d_in, const int* in_sizes, int n_in,
                              void* d_out, int out_size)
{
    (void)in_sizes; (void)n_in; (void)out_size;
    const float* x     = (const float*)d_in[0];
    const float* W_in  = (const float*)d_in[1];
    const float* W_out = (const float*)d_in[16];
    float* out = (float*)d_out;

    float *p_xz, *p_xc, *p_dbc, *p_dbcp, *p_delta, *p_y;
    cudaGetSymbolAddress((void**)&p_xz,    g_xz);
    cudaGetSymbolAddress((void**)&p_xc,    g_xconv);
    cudaGetSymbolAddress((void**)&p_dbc,   g_dbc);
    cudaGetSymbolAddress((void**)&p_dbcp,  g_dbcp);
    cudaGetSymbolAddress((void**)&p_delta, g_delta);
    cudaGetSymbolAddress((void**)&p_y,     g_y);

    // 1) xz = x @ W_in.T : (2048 x 4096), K=1024
    tgemm_nt<<<dim3(2 * ED / 128, MROWS / 128, 1), 256>>>(
        x, DM, W_in, DM, p_xz, 2 * ED, MROWS, 2 * ED, DM, DM, 0, nullptr);

    for (int dir = 0; dir < 2; dir++) {
        const float* cw   = (const float*)d_in[dir ? 9  : 2];
        const float* cb   = (const float*)d_in[dir ? 10 : 3];
        const float* Wx   = (const float*)d_in[dir ? 11 : 4];
        const float* Wdt  = (const float*)d_in[dir ? 12 : 5];
        const float* bdt  = (const float*)d_in[dir ? 13 : 6];
        const float* Alog = (const float*)d_in[dir ? 14 : 7];
        const float* Dpv  = (const float*)d_in[dir ? 15 : 8];

        // 2) conv + silu
        conv_silu_kernel<<<(MROWS * ED) / 256, 256>>>(p_xz, cw, cb, p_xc, dir);

        // 3) dbc = xconv @ Wx.T : (2048 x 96), K=2048, split-K x8
        tgemm_nt<<<dim3(1, MROWS / 128, SPLITS), 256>>>(
            p_xc, ED, Wx, ED, p_dbcp, KX, MROWS, KX, ED, ED / SPLITS, 0, nullptr);
        reduce_splits<<<(MROWS * KX + 255) / 256, 256>>>(p_dbcp, p_dbc, MROWS * KX);

        // 4) delta = softplus(dbc[:, :64] @ Wdt.T + b_dt) : (2048 x 2048), K=64
        tgemm_nt<<<dim3(ED / 128, MROWS / 128, 1), 256>>>(
            p_dbc, KX, Wdt, DTR, p_delta, ED, MROWS, ED, DTR, DTR, 1, bdt);

        // 5) selective scan (+ gate, + combine for bwd branch)
        scan_kernel<<<B_SZ * (ED / 32), 128>>>(
            p_delta, p_xc, p_dbc, p_xz, Alog, Dpv, p_y, dir);
    }

    // 6) out = ycomb @ W_out.T : (2048 x 1024), K=2048
    tgemm_nt<<<dim3(DM / 128, MROWS / 128, 1), 256>>>(
        p_y, ED, W_out, ED, out, DM, MROWS, DM, ED, ED, 0, nullptr);
}

// round 5
// speedup vs baseline: 1.7438x; 1.5142x over previous
#include <cuda_runtime.h>
#include <math.h>

#define B_SZ 4
#define LSEQ 512
#define DM   1024
#define ED   2048
#define NS   16
#define DTR  64
#define KX   96                 // DTR + 2*NS
#define MROWS (B_SZ*LSEQ)       // 2048
#define SPLITS 8
#define NED   ((size_t)MROWS * ED)
#define NDBC  ((size_t)MROWS * KX)

// ---------------- scratch (static device globals; no runtime allocation) ----
__device__ __align__(16) float g_xz   [(size_t)MROWS * 2 * ED];       // 32 MB
__device__ __align__(16) float g_xconv[2 * NED];                      // 32 MB
__device__ __align__(16) float g_dbc  [2 * NDBC];
__device__ __align__(16) float g_dbcp [2 * (size_t)SPLITS * NDBC];
__device__ __align__(16) float g_delta[2 * NED];                      // 32 MB
__device__ __align__(16) float g_y    [2 * NED];                      // 32 MB

__device__ __forceinline__ float sigmoidf_(float v) {
    return 1.f / (1.f + __expf(-v));
}

// smem column swizzle: conflict-free for both the staging STS pattern and the
// MMA fragment LDS pattern (flips bits 3..4 of the column by row bits 2..3).
__device__ __forceinline__ int SW(int r, int c) { return c ^ ((r & 12) << 1); }

// ---------------------------------------------------------------------------
// tf32 warp MMA m16n8k8 (row.col): D = A*B + C  (C in-place)
// ---------------------------------------------------------------------------
__device__ __forceinline__ void mma_tf32(float c[4],
                                         unsigned a0, unsigned a1,
                                         unsigned a2, unsigned a3,
                                         unsigned b0, unsigned b1)
{
    asm volatile(
        "mma.sync.aligned.m16n8k8.row.col.f32.tf32.tf32.f32 "
        "{%0,%1,%2,%3}, {%4,%5,%6,%7}, {%8,%9}, {%0,%1,%2,%3};\n"
        : "+f"(c[0]), "+f"(c[1]), "+f"(c[2]), "+f"(c[3])
        : "r"(a0), "r"(a1), "r"(a2), "r"(a3), "r"(b0), "r"(b1));
}

__device__ __forceinline__ void split_tf32(float v, float& hi, float& lo)
{
    unsigned u;
    asm("cvt.rna.tf32.f32 %0, %1;" : "=r"(u) : "f"(v));
    hi = __uint_as_float(u);
    lo = v - hi;
}

// ---------------------------------------------------------------------------
// Tensor-core NT GEMM (compensated tf32, 3-MMA): C[m,n] = sum_k A[m,k]*B[n,k]
// BM=BN=128, BK=16, 256 threads = 8 warps (2x4), warp tile 64x32.
// blockIdx.z = dir*zdiv + k-split s. A offset by dir*sAdir, weights/bias
// selected by dir, C offset dir*sCdir + s*M*ldc.
// If A2 != null: A-operand = 0.5*(A + A2) elementwise (bidir combine).
// epi1 = softplus(v + bias[n]) via MUFU.
// ---------------------------------------------------------------------------
__global__ __launch_bounds__(256) void tgemm_nt(
    const float* __restrict__ A, const float* __restrict__ A2, int lda, size_t sAdir,
    const float* __restrict__ B0, const float* __restrict__ B1, int ldb,
    float* __restrict__ C, int ldc, size_t sCdir,
    int M, int N, int Ktot, int ksz, int zdiv,
    int epi, const float* __restrict__ bias0, const float* __restrict__ bias1)
{
    __shared__ float Ah[16][136], Al[16][136];
    __shared__ float Bh[16][136], Bl[16][136];

    const int bm  = blockIdx.y * 128;
    const int bn  = blockIdx.x * 128;
    const int dir = blockIdx.z / zdiv;
    const int s   = blockIdx.z % zdiv;
    const int k0  = s * ksz;
    int k1 = k0 + ksz; if (k1 > Ktot) k1 = Ktot;

    const float* Ab  = A + (size_t)dir * sAdir;
    const float* Bw  = dir ? B1 : B0;
    const float* bias = dir ? bias1 : bias0;
    float* Cout = C + (size_t)dir * sCdir + (size_t)s * (size_t)M * (size_t)ldc;

    const int tid  = threadIdx.x;
    const int warp = tid >> 5, lane = tid & 31;
    const int wm = (warp >> 2) * 64;
    const int wn = (warp & 3) * 32;
    const int qr = lane >> 2;              // 0..7
    const int qc = lane & 3;               // 0..3

    const int gr = tid >> 2;               // 0..63
    const int gc = (tid & 3) * 4;          // 0,4,8,12
    const bool bval0 = (bn + gr)      < N;
    const bool bval1 = (bn + gr + 64) < N;
    const float* Ap0 = Ab + (size_t)(bm + gr)      * lda + gc;
    const float* Ap1 = Ab + (size_t)(bm + gr + 64) * lda + gc;
    const float* Bp0 = Bw + (size_t)(bn + gr)      * ldb + gc;
    const float* Bp1 = Bw + (size_t)(bn + gr + 64) * ldb + gc;
    const float* A2p0 = A2 ? A2 + (size_t)(bm + gr)      * lda + gc : nullptr;
    const float* A2p1 = A2 ? A2 + (size_t)(bm + gr + 64) * lda + gc : nullptr;

    float acc[4][4][4];
#pragma unroll
    for (int i = 0; i < 4; i++)
#pragma unroll
        for (int j = 0; j < 4; j++)
#pragma unroll
            for (int r = 0; r < 4; r++) acc[i][j][r] = 0.f;

    float4 av0, av1, bv0, bv1;
    const float4 z4 = make_float4(0.f, 0.f, 0.f, 0.f);

    auto loadA = [&](const float* p, const float* p2, int k) -> float4 {
        float4 v = *reinterpret_cast<const float4*>(p + k);
        if (p2) {
            float4 w = *reinterpret_cast<const float4*>(p2 + k);
            v.x = 0.5f * (v.x + w.x); v.y = 0.5f * (v.y + w.y);
            v.z = 0.5f * (v.z + w.z); v.w = 0.5f * (v.w + w.w);
        }
        return v;
    };

    av0 = loadA(Ap0, A2p0, k0);
    av1 = loadA(Ap1, A2p1, k0);
    bv0 = bval0 ? *reinterpret_cast<const float4*>(Bp0 + k0) : z4;
    bv1 = bval1 ? *reinterpret_cast<const float4*>(Bp1 + k0) : z4;

    for (int k = k0; k < k1; k += 16) {
        {
            const float a0v[4] = {av0.x, av0.y, av0.z, av0.w};
            const float a1v[4] = {av1.x, av1.y, av1.z, av1.w};
            const float b0v[4] = {bv0.x, bv0.y, bv0.z, bv0.w};
            const float b1v[4] = {bv1.x, bv1.y, bv1.z, bv1.w};
#pragma unroll
            for (int j = 0; j < 4; j++) {
                const int r = gc + j;                 // smem row
                const int c0 = SW(r, gr), c1 = SW(r, gr + 64);
                float h, l;
                split_tf32(a0v[j], h, l); Ah[r][c0] = h; Al[r][c0] = l;
                split_tf32(a1v[j], h, l); Ah[r][c1] = h; Al[r][c1] = l;
                split_tf32(b0v[j], h, l); Bh[r][c0] = h; Bl[r][c0] = l;
                split_tf32(b1v[j], h, l); Bh[r][c1] = h; Bl[r][c1] = l;
            }
        }
        __syncthreads();

        if (k + 16 < k1) {
            av0 = loadA(Ap0, A2p0, k + 16);
            av1 = loadA(Ap1, A2p1, k + 16);
            bv0 = bval0 ? *reinterpret_cast<const float4*>(Bp0 + k + 16) : z4;
            bv1 = bval1 ? *reinterpret_cast<const float4*>(Bp1 + k + 16) : z4;
        }

#pragma unroll
        for (int kk = 0; kk < 16; kk += 8) {
            const int r0 = kk + qc, r1 = kk + qc + 4;
            unsigned bfh[4][2], bfl[4][2];
#pragma unroll
            for (int j = 0; j < 4; j++) {
                const int n0 = wn + j * 8;
                bfh[j][0] = __float_as_uint(Bh[r0][SW(r0, n0 + qr)]);
                bfh[j][1] = __float_as_uint(Bh[r1][SW(r1, n0 + qr)]);
                bfl[j][0] = __float_as_uint(Bl[r0][SW(r0, n0 + qr)]);
                bfl[j][1] = __float_as_uint(Bl[r1][SW(r1, n0 + qr)]);
            }
#pragma unroll
            for (int i = 0; i < 4; i++) {
                const int m0 = wm + i * 16;
                unsigned ah0 = __float_as_uint(Ah[r0][SW(r0, m0 + qr)]);
                unsigned ah1 = __float_as_uint(Ah[r0][SW(r0, m0 + qr + 8)]);
                unsigned ah2 = __float_as_uint(Ah[r1][SW(r1, m0 + qr)]);
                unsigned ah3 = __float_as_uint(Ah[r1][SW(r1, m0 + qr + 8)]);
                unsigned al0 = __float_as_uint(Al[r0][SW(r0, m0 + qr)]);
                unsigned al1 = __float_as_uint(Al[r0][SW(r0, m0 + qr + 8)]);
                unsigned al2 = __float_as_uint(Al[r1][SW(r1, m0 + qr)]);
                unsigned al3 = __float_as_uint(Al[r1][SW(r1, m0 + qr + 8)]);
#pragma unroll
                for (int j = 0; j < 4; j++) {
                    mma_tf32(acc[i][j], ah0, ah1, ah2, ah3, bfh[j][0], bfh[j][1]);
                    mma_tf32(acc[i][j], al0, al1, al2, al3, bfh[j][0], bfh[j][1]);
                    mma_tf32(acc[i][j], ah0, ah1, ah2, ah3, bfl[j][0], bfl[j][1]);
                }
            }
        }
        __syncthreads();
    }

#pragma unroll
    for (int i = 0; i < 4; i++) {
        const int row0 = bm + wm + i * 16 + qr;
#pragma unroll
        for (int j = 0; j < 4; j++) {
            const int col0 = bn + wn + j * 8 + qc * 2;
#pragma unroll
            for (int r = 0; r < 4; r++) {
                const int rr = row0 + (r >> 1) * 8;
                const int cc = col0 + (r & 1);
                if (cc < N) {
                    float v = acc[i][j][r];
                    if (epi == 1) {
                        v += bias[cc];
                        v = (v > 15.f) ? v : __logf(1.f + __expf(v));  // fast softplus
                    }
                    Cout[(size_t)rr * ldc + cc] = v;
                }
            }
        }
    }
}

// ---------------------------------------------------------------------------
// Reduce split-K partials for both dirs.
// part layout: [dir][split][n1], out: [dir][n1]
// ---------------------------------------------------------------------------
__global__ void reduce_splits(const float* __restrict__ part,
                              float* __restrict__ outp, int n1)
{
    int i = blockIdx.x * blockDim.x + threadIdx.x;
    if (i >= 2 * n1) return;
    int dir = i / n1, ii = i - dir * n1;
    const float* p = part + (size_t)dir * SPLITS * n1;
    float s = 0.f;
#pragma unroll
    for (int j = 0; j < SPLITS; j++) s += p[(size_t)j * n1 + ii];
    outp[i] = s;
}

// ---------------------------------------------------------------------------
// Causal depthwise conv (K=4) + SiLU, both directions in one launch.
// ---------------------------------------------------------------------------
__global__ __launch_bounds__(256) void conv_silu_kernel(
    const float* __restrict__ xz,
    const float* __restrict__ w0, const float* __restrict__ cb0,
    const float* __restrict__ w1, const float* __restrict__ cb1,
    float* __restrict__ xc)
{
    size_t idx = (size_t)blockIdx.x * blockDim.x + threadIdx.x;
    if (idx >= 2 * NED) return;
    const int dir = (int)(idx / NED);
    size_t loc = idx - (size_t)dir * NED;
    int e = (int)(loc % ED);
    int t = (int)((loc / ED) % LSEQ);
    int b = (int)(loc / ((size_t)ED * LSEQ));
    const float* w  = dir ? w1  : w0;
    const float* cb = dir ? cb1 : cb0;

    float acc = cb[e];
#pragma unroll
    for (int i = 0; i < 4; i++) {
        int tau = t - 3 + i;
        if (tau >= 0) {
            int tt = dir ? (LSEQ - 1 - tau) : tau;
            acc = fmaf(w[e * 4 + i],
                       xz[((size_t)b * LSEQ + tt) * (2 * ED) + e], acc);
        }
    }
    xc[idx] = acc * sigmoidf_(acc);
}

// ---------------------------------------------------------------------------
// Selective scan, both directions in one launch (512 blocks x 128 threads).
// dir=d writes y[d] in ORIGINAL time order (bwd branch writes reversed rows).
// ---------------------------------------------------------------------------
__global__ __launch_bounds__(128) void scan_kernel(
    const float* __restrict__ delta,   // [2][MROWS][ED] branch time order
    const float* __restrict__ xconv,   // [2][MROWS][ED]
    const float* __restrict__ dbc,     // [2][MROWS][96]
    const float* __restrict__ xz,      // [MROWS][2*ED] original time order
    const float* __restrict__ A0, const float* __restrict__ A1,
    const float* __restrict__ D0, const float* __restrict__ D1,
    float* __restrict__ y)             // [2][MROWS][ED]
{
    const int dir = blockIdx.x >> 8;
    const int rb  = blockIdx.x & 255;
    const int b   = rb >> 6;
    const int ec  = rb & 63;
    const int tid = threadIdx.x;
    const int e = ec * 32 + (tid >> 2);
    const int g = tid & 3;

    const float* dlt = delta + (size_t)dir * NED;
    const float* xcv = xconv + (size_t)dir * NED;
    const float* dbcd = dbc + (size_t)dir * NDBC;
    const float* A_log = dir ? A1 : A0;
    const float* Dp    = dir ? D1 : D0;
    float* yo = y + (size_t)dir * NED;

    float4 al = *reinterpret_cast<const float4*>(&A_log[e * NS + g * 4]);
    const float Aa = -__expf(al.x), Ab = -__expf(al.y),
                Ac = -__expf(al.z), Ad = -__expf(al.w);
    const float dp = Dp[e];

    float h0 = 0.f, h1 = 0.f, h2 = 0.f, h3 = 0.f;
    const size_t baseBL = (size_t)b * LSEQ;

    for (int t = 0; t < LSEQ; t++) {
        const size_t row = baseBL + t;
        const float d  = dlt[row * ED + e];
        const float xv = xcv[row * ED + e];
        const int   tt = dir ? (LSEQ - 1 - t) : t;
        const float zv = xz[(baseBL + tt) * (2 * ED) + ED + e];
        float4 Bv = *reinterpret_cast<const float4*>(&dbcd[row * KX + DTR + g * 4]);
        float4 Cv = *reinterpret_cast<const float4*>(&dbcd[row * KX + DTR + NS + g * 4]);

        const float dx = d * xv;
        h0 = fmaf(__expf(d * Aa), h0, dx * Bv.x);
        h1 = fmaf(__expf(d * Ab), h1, dx * Bv.y);
        h2 = fmaf(__expf(d * Ac), h2, dx * Bv.z);
        h3 = fmaf(__expf(d * Ad), h3, dx * Bv.w);

        float yp = h0 * Cv.x + h1 * Cv.y + h2 * Cv.z + h3 * Cv.w;
        yp += __shfl_xor_sync(0xffffffffu, yp, 1);
        yp += __shfl_xor_sync(0xffffffffu, yp, 2);

        if (g == 0) {
            float yt  = yp + dp * xv;
            float val = yt * (zv * sigmoidf_(zv));
            size_t orow = dir ? (baseBL + (LSEQ - 1 - t)) : row;
            yo[orow * ED + e] = val;
        }
    }
}

// ---------------------------------------------------------------------------
extern "C" void kernel_launch(void* const* d_in, const int* in_sizes, int n_in,
                              void* d_out, int out_size)
{
    (void)in_sizes; (void)n_in; (void)out_size;
    const float* x     = (const float*)d_in[0];
    const float* W_in  = (const float*)d_in[1];
    const float* cw0   = (const float*)d_in[2];
    const float* cb0   = (const float*)d_in[3];
    const float* Wx0   = (const float*)d_in[4];
    const float* Wdt0  = (const float*)d_in[5];
    const float* bdt0  = (const float*)d_in[6];
    const float* Al0   = (const float*)d_in[7];
    const float* Dp0   = (const float*)d_in[8];
    const float* cw1   = (const float*)d_in[9];
    const float* cb1   = (const float*)d_in[10];
    const float* Wx1   = (const float*)d_in[11];
    const float* Wdt1  = (const float*)d_in[12];
    const float* bdt1  = (const float*)d_in[13];
    const float* Al1   = (const float*)d_in[14];
    const float* Dp1   = (const float*)d_in[15];
    const float* W_out = (const float*)d_in[16];
    float* out = (float*)d_out;

    float *p_xz, *p_xc, *p_dbc, *p_dbcp, *p_delta, *p_y;
    cudaGetSymbolAddress((void**)&p_xz,    g_xz);
    cudaGetSymbolAddress((void**)&p_xc,    g_xconv);
    cudaGetSymbolAddress((void**)&p_dbc,   g_dbc);
    cudaGetSymbolAddress((void**)&p_dbcp,  g_dbcp);
    cudaGetSymbolAddress((void**)&p_delta, g_delta);
    cudaGetSymbolAddress((void**)&p_y,     g_y);

    // 0) xz = x @ W_in.T : (2048 x 4096), K=1024
    tgemm_nt<<<dim3(2 * ED / 128, MROWS / 128, 1), 256>>>(
        x, nullptr, DM, 0, W_in, W_in, DM, p_xz, 2 * ED, 0,
        MROWS, 2 * ED, DM, DM, 1, 0, nullptr, nullptr);

    // 1) conv + silu, both dirs
    conv_silu_kernel<<<(unsigned)((2 * NED + 255) / 256), 256>>>(
        p_xz, cw0, cb0, cw1, cb1, p_xc);

    // 2) dbc partials = xconv @ Wx.T : (2048 x 96), K=2048, split-K x8, both dirs
    tgemm_nt<<<dim3(1, MROWS / 128, 2 * SPLITS), 256>>>(
        p_xc, nullptr, ED, NED, Wx0, Wx1, ED, p_dbcp, KX, (size_t)SPLITS * NDBC,
        MROWS, KX, ED, ED / SPLITS, SPLITS, 0, nullptr, nullptr);

    // 3) reduce partials
    reduce_splits<<<(unsigned)((2 * NDBC + 255) / 256), 256>>>(
        p_dbcp, p_dbc, (int)NDBC);

    // 4) delta = softplus(dbc[:, :64] @ Wdt.T + b_dt) : (2048 x 2048), K=64, both dirs
    tgemm_nt<<<dim3(ED / 128, MROWS / 128, 2), 256>>>(
        p_dbc, nullptr, KX, NDBC, Wdt0, Wdt1, DTR, p_delta, ED, NED,
        MROWS, ED, DTR, DTR, 1, 1, bdt0, bdt1);

    // 5) selective scan, both dirs
    scan_kernel<<<512, 128>>>(p_delta, p_xc, p_dbc, p_xz,
                              Al0, Al1, Dp0, Dp1, p_y);

    // 6) out = 0.5*(y0+y1) @ W_out.T : (2048 x 1024), K=2048
    tgemm_nt<<<dim3(DM / 128, MROWS / 128, 1), 256>>>(
        p_y, p_y + NED, ED, 0, W_out, W_out, ED, out, DM, 0,
        MROWS, DM, ED, ED, 1, 0, nullptr, nullptr);
}

// round 7
// speedup vs baseline: 1.9803x; 1.1356x over previous
#include <cuda_runtime.h>
#include <cuda_bf16.h>
#include <math.h>

#define B_SZ 4
#define LSEQ 512
#define DM   1024
#define ED   2048
#define NS   16
#define DTR  64
#define KX   96                 // DTR + 2*NS
#define MROWS (B_SZ*LSEQ)       // 2048
#define SPLITS 8
#define NED   ((size_t)MROWS * ED)
#define NDBC  ((size_t)MROWS * KX)

// ---------------- scratch (static device globals; no runtime allocation) ----
__device__ __align__(16) float g_xz   [(size_t)MROWS * 2 * ED];       // 32 MB
__device__ __align__(16) float g_xconv[2 * NED];                      // 32 MB
__device__ __align__(16) float g_dbc  [2 * NDBC];
__device__ __align__(16) float g_dbcp [2 * (size_t)SPLITS * NDBC];
__device__ __align__(16) float g_delta[2 * NED];                      // 32 MB
__device__ __align__(16) float g_y    [2 * NED];                      // 32 MB

__device__ __forceinline__ float sigmoidf_(float v) {
    return 1.f / (1.f + __expf(-v));
}

// bf16 m16n8k16 MMA (row.col), fp32 accumulate in-place.
__device__ __forceinline__ void mma_bf16(float c[4],
                                         unsigned a0, unsigned a1,
                                         unsigned a2, unsigned a3,
                                         unsigned b0, unsigned b1)
{
    asm volatile(
        "mma.sync.aligned.m16n8k16.row.col.f32.bf16.bf16.f32 "
        "{%0,%1,%2,%3}, {%4,%5,%6,%7}, {%8,%9}, {%0,%1,%2,%3};\n"
        : "+f"(c[0]), "+f"(c[1]), "+f"(c[2]), "+f"(c[3])
        : "r"(a0), "r"(a1), "r"(a2), "r"(a3), "r"(b0), "r"(b1));
}

// Split v0,v1 into packed bf16 hi-pair and lo-pair (v0 in low half = even k).
__device__ __forceinline__ void pack_split(float v0, float v1,
                                           unsigned& hi, unsigned& lo)
{
    __nv_bfloat16 h0 = __float2bfloat16(v0);
    __nv_bfloat16 h1 = __float2bfloat16(v1);
    float r0 = v0 - __bfloat162float(h0);
    float r1 = v1 - __bfloat162float(h1);
    __nv_bfloat16 l0 = __float2bfloat16(r0);
    __nv_bfloat16 l1 = __float2bfloat16(r1);
    hi = (unsigned)__bfloat16_as_ushort(h0) | ((unsigned)__bfloat16_as_ushort(h1) << 16);
    lo = (unsigned)__bfloat16_as_ushort(l0) | ((unsigned)__bfloat16_as_ushort(l1) << 16);
}

// smem column swizzle: conflict-free fragment LDS (banks = 8*(p&3) + qr + m0)
__device__ __forceinline__ int SWC(int p, int c) { return c ^ ((p & 3) << 3); }

// ---------------------------------------------------------------------------
// Tensor-core NT GEMM (compensated bf16, 3-MMA): C[m,n] = sum_k A[m,k]*B[n,k]
// BM=BN=128, BK=16, 256 threads = 8 warps (2x4), warp tile 64x32.
// blockIdx.z = dir*zdiv + k-split s. If A2 != null: A-op = 0.5*(A+A2).
// epi1 = softplus(v + bias[n]) via MUFU.
// ---------------------------------------------------------------------------
__global__ __launch_bounds__(256) void tgemm_nt(
    const float* __restrict__ A, const float* __restrict__ A2, int lda, size_t sAdir,
    const float* __restrict__ B0, const float* __restrict__ B1, int ldb,
    float* __restrict__ C, int ldc, size_t sCdir,
    int M, int N, int Ktot, int ksz, int zdiv,
    int epi, const float* __restrict__ bias0, const float* __restrict__ bias1)
{
    __shared__ unsigned Ah2[8][128], Al2[8][128];
    __shared__ unsigned Bh2[8][128], Bl2[8][128];

    const int bm  = blockIdx.y * 128;
    const int bn  = blockIdx.x * 128;
    const int dir = blockIdx.z / zdiv;
    const int s   = blockIdx.z % zdiv;
    const int k0  = s * ksz;
    int k1 = k0 + ksz; if (k1 > Ktot) k1 = Ktot;

    const float* Ab   = A + (size_t)dir * sAdir;
    const float* Bw   = dir ? B1 : B0;
    const float* bias = dir ? bias1 : bias0;
    float* Cout = C + (size_t)dir * sCdir + (size_t)s * (size_t)M * (size_t)ldc;

    const int tid  = threadIdx.x;
    const int warp = tid >> 5, lane = tid & 31;
    const int wm = (warp >> 2) * 64;
    const int wn = (warp & 3) * 32;
    const int qr = lane >> 2;              // 0..7
    const int qc = lane & 3;               // 0..3

    const int gr = tid >> 2;               // 0..63
    const int gc = (tid & 3) * 4;          // 0,4,8,12 (k offset)
    const int p0 = gc >> 1, p1 = p0 + 1;   // k-pair rows
    const bool bval0 = (bn + gr)      < N;
    const bool bval1 = (bn + gr + 64) < N;
    const float* Ap0 = Ab + (size_t)(bm + gr)      * lda + gc;
    const float* Ap1 = Ab + (size_t)(bm + gr + 64) * lda + gc;
    const float* Bp0 = Bw + (size_t)(bn + gr)      * ldb + gc;
    const float* Bp1 = Bw + (size_t)(bn + gr + 64) * ldb + gc;
    const float* A2p0 = A2 ? A2 + (size_t)(bm + gr)      * lda + gc : nullptr;
    const float* A2p1 = A2 ? A2 + (size_t)(bm + gr + 64) * lda + gc : nullptr;

    float acc[4][4][4];
#pragma unroll
    for (int i = 0; i < 4; i++)
#pragma unroll
        for (int j = 0; j < 4; j++)
#pragma unroll
            for (int r = 0; r < 4; r++) acc[i][j][r] = 0.f;

    float4 av0, av1, bv0, bv1;
    const float4 z4 = make_float4(0.f, 0.f, 0.f, 0.f);

    auto loadA = [&](const float* p, const float* p2, int k) -> float4 {
        float4 v = *reinterpret_cast<const float4*>(p + k);
        if (p2) {
            float4 w = *reinterpret_cast<const float4*>(p2 + k);
            v.x = 0.5f * (v.x + w.x); v.y = 0.5f * (v.y + w.y);
            v.z = 0.5f * (v.z + w.z); v.w = 0.5f * (v.w + w.w);
        }
        return v;
    };

    av0 = loadA(Ap0, A2p0, k0);
    av1 = loadA(Ap1, A2p1, k0);
    bv0 = bval0 ? *reinterpret_cast<const float4*>(Bp0 + k0) : z4;
    bv1 = bval1 ? *reinterpret_cast<const float4*>(Bp1 + k0) : z4;

    for (int k = k0; k < k1; k += 16) {
        {
            unsigned h, l;
            pack_split(av0.x, av0.y, h, l); Ah2[p0][SWC(p0, gr)]      = h; Al2[p0][SWC(p0, gr)]      = l;
            pack_split(av0.z, av0.w, h, l); Ah2[p1][SWC(p1, gr)]      = h; Al2[p1][SWC(p1, gr)]      = l;
            pack_split(av1.x, av1.y, h, l); Ah2[p0][SWC(p0, gr + 64)] = h; Al2[p0][SWC(p0, gr + 64)] = l;
            pack_split(av1.z, av1.w, h, l); Ah2[p1][SWC(p1, gr + 64)] = h; Al2[p1][SWC(p1, gr + 64)] = l;
            pack_split(bv0.x, bv0.y, h, l); Bh2[p0][SWC(p0, gr)]      = h; Bl2[p0][SWC(p0, gr)]      = l;
            pack_split(bv0.z, bv0.w, h, l); Bh2[p1][SWC(p1, gr)]      = h; Bl2[p1][SWC(p1, gr)]      = l;
            pack_split(bv1.x, bv1.y, h, l); Bh2[p0][SWC(p0, gr + 64)] = h; Bl2[p0][SWC(p0, gr + 64)] = l;
            pack_split(bv1.z, bv1.w, h, l); Bh2[p1][SWC(p1, gr + 64)] = h; Bl2[p1][SWC(p1, gr + 64)] = l;
        }
        __syncthreads();

        if (k + 16 < k1) {
            av0 = loadA(Ap0, A2p0, k + 16);
            av1 = loadA(Ap1, A2p1, k + 16);
            bv0 = bval0 ? *reinterpret_cast<const float4*>(Bp0 + k + 16) : z4;
            bv1 = bval1 ? *reinterpret_cast<const float4*>(Bp1 + k + 16) : z4;
        }

        // fragments: k-pairs qc (k=2qc,2qc+1) and qc+4 (k=2qc+8,2qc+9)
        unsigned bh0[4], bh1[4], bl0[4], bl1[4];
#pragma unroll
        for (int j = 0; j < 4; j++) {
            const int n0 = wn + j * 8 + qr;
            bh0[j] = Bh2[qc][SWC(qc, n0)];
            bh1[j] = Bh2[qc + 4][SWC(qc, n0)];
            bl0[j] = Bl2[qc][SWC(qc, n0)];
            bl1[j] = Bl2[qc + 4][SWC(qc, n0)];
        }
#pragma unroll
        for (int i = 0; i < 4; i++) {
            const int m0 = wm + i * 16 + qr;
            unsigned ah0 = Ah2[qc][SWC(qc, m0)];
            unsigned ah1 = Ah2[qc][SWC(qc, m0 + 8)];
            unsigned ah2 = Ah2[qc + 4][SWC(qc, m0)];
            unsigned ah3 = Ah2[qc + 4][SWC(qc, m0 + 8)];
            unsigned al0 = Al2[qc][SWC(qc, m0)];
            unsigned al1 = Al2[qc][SWC(qc, m0 + 8)];
            unsigned al2 = Al2[qc + 4][SWC(qc, m0)];
            unsigned al3 = Al2[qc + 4][SWC(qc, m0 + 8)];
#pragma unroll
            for (int j = 0; j < 4; j++) {
                mma_bf16(acc[i][j], ah0, ah1, ah2, ah3, bh0[j], bh1[j]);
                mma_bf16(acc[i][j], al0, al1, al2, al3, bh0[j], bh1[j]);
                mma_bf16(acc[i][j], ah0, ah1, ah2, ah3, bl0[j], bl1[j]);
            }
        }
        __syncthreads();
    }

    // epilogue: (c0,c1)=(qr,2qc..2qc+1), (c2,c3)=(qr+8,..) -> float2 stores
#pragma unroll
    for (int i = 0; i < 4; i++) {
        const int row0 = bm + wm + i * 16 + qr;
#pragma unroll
        for (int j = 0; j < 4; j++) {
            const int cc = bn + wn + j * 8 + qc * 2;
            if (cc < N) {   // N even, cc even -> pair fully valid
#pragma unroll
                for (int half = 0; half < 2; half++) {
                    const int rr = row0 + half * 8;
                    float v0 = acc[i][j][half * 2];
                    float v1 = acc[i][j][half * 2 + 1];
                    if (epi == 1) {
                        v0 += bias[cc];
                        v1 += bias[cc + 1];
                        v0 = (v0 > 15.f) ? v0 : __logf(1.f + __expf(v0));
                        v1 = (v1 > 15.f) ? v1 : __logf(1.f + __expf(v1));
                    }
                    *reinterpret_cast<float2*>(&Cout[(size_t)rr * ldc + cc]) =
                        make_float2(v0, v1);
                }
            }
        }
    }
}

// ---------------------------------------------------------------------------
// Reduce split-K partials for both dirs.
// ---------------------------------------------------------------------------
__global__ void reduce_splits(const float* __restrict__ part,
                              float* __restrict__ outp, int n1)
{
    int i = blockIdx.x * blockDim.x + threadIdx.x;
    if (i >= 2 * n1) return;
    int dir = i / n1, ii = i - dir * n1;
    const float* p = part + (size_t)dir * SPLITS * n1;
    float s = 0.f;
#pragma unroll
    for (int j = 0; j < SPLITS; j++) s += p[(size_t)j * n1 + ii];
    outp[i] = s;
}

// ---------------------------------------------------------------------------
// Causal depthwise conv (K=4) + SiLU, both directions in one launch.
// ---------------------------------------------------------------------------
__global__ __launch_bounds__(256) void conv_silu_kernel(
    const float* __restrict__ xz,
    const float* __restrict__ w0, const float* __restrict__ cb0,
    const float* __restrict__ w1, const float* __restrict__ cb1,
    float* __restrict__ xc)
{
    size_t idx = (size_t)blockIdx.x * blockDim.x + threadIdx.x;
    if (idx >= 2 * NED) return;
    const int dir = (int)(idx / NED);
    size_t loc = idx - (size_t)dir * NED;
    int e = (int)(loc % ED);
    int t = (int)((loc / ED) % LSEQ);
    int b = (int)(loc / ((size_t)ED * LSEQ));
    const float* w  = dir ? w1  : w0;
    const float* cb = dir ? cb1 : cb0;

    float acc = cb[e];
#pragma unroll
    for (int i = 0; i < 4; i++) {
        int tau = t - 3 + i;
        if (tau >= 0) {
            int tt = dir ? (LSEQ - 1 - tau) : tau;
            acc = fmaf(w[e * 4 + i],
                       xz[((size_t)b * LSEQ + tt) * (2 * ED) + e], acc);
        }
    }
    xc[idx] = acc * sigmoidf_(acc);
}

// ---------------------------------------------------------------------------
// Selective scan, both directions in one launch (512 blocks x 128 threads).
// ---------------------------------------------------------------------------
__global__ __launch_bounds__(128) void scan_kernel(
    const float* __restrict__ delta,
    const float* __restrict__ xconv,
    const float* __restrict__ dbc,
    const float* __restrict__ xz,
    const float* __restrict__ A0, const float* __restrict__ A1,
    const float* __restrict__ D0, const float* __restrict__ D1,
    float* __restrict__ y)
{
    const int dir = blockIdx.x >> 8;
    const int rb  = blockIdx.x & 255;
    const int b   = rb >> 6;
    const int ec  = rb & 63;
    const int tid = threadIdx.x;
    const int e = ec * 32 + (tid >> 2);
    const int g = tid & 3;

    const float* dlt  = delta + (size_t)dir * NED;
    const float* xcv  = xconv + (size_t)dir * NED;
    const float* dbcd = dbc + (size_t)dir * NDBC;
    const float* A_log = dir ? A1 : A0;
    const float* Dp    = dir ? D1 : D0;
    float* yo = y + (size_t)dir * NED;

    float4 al = *reinterpret_cast<const float4*>(&A_log[e * NS + g * 4]);
    const float Aa = -__expf(al.x), Ab = -__expf(al.y),
                Ac = -__expf(al.z), Ad = -__expf(al.w);
    const float dp = Dp[e];

    float h0 = 0.f, h1 = 0.f, h2 = 0.f, h3 = 0.f;
    const size_t baseBL = (size_t)b * LSEQ;

    for (int t = 0; t < LSEQ; t++) {
        const size_t row = baseBL + t;
        const float d  = dlt[row * ED + e];
        const float xv = xcv[row * ED + e];
        const int   tt = dir ? (LSEQ - 1 - t) : t;
        const float zv = xz[(baseBL + tt) * (2 * ED) + ED + e];
        float4 Bv = *reinterpret_cast<const float4*>(&dbcd[row * KX + DTR + g * 4]);
        float4 Cv = *reinterpret_cast<const float4*>(&dbcd[row * KX + DTR + NS + g * 4]);

        const float dx = d * xv;
        h0 = fmaf(__expf(d * Aa), h0, dx * Bv.x);
        h1 = fmaf(__expf(d * Ab), h1, dx * Bv.y);
        h2 = fmaf(__expf(d * Ac), h2, dx * Bv.z);
        h3 = fmaf(__expf(d * Ad), h3, dx * Bv.w);

        float yp = h0 * Cv.x + h1 * Cv.y + h2 * Cv.z + h3 * Cv.w;
        yp += __shfl_xor_sync(0xffffffffu, yp, 1);
        yp += __shfl_xor_sync(0xffffffffu, yp, 2);

        if (g == 0) {
            float yt  = yp + dp * xv;
            float val = yt * (zv * sigmoidf_(zv));
            size_t orow = dir ? (baseBL + (LSEQ - 1 - t)) : row;
            yo[orow * ED + e] = val;
        }
    }
}

// ---------------------------------------------------------------------------
extern "C" void kernel_launch(void* const* d_in, const int* in_sizes, int n_in,
                              void* d_out, int out_size)
{
    (void)in_sizes; (void)n_in; (void)out_size;
    const float* x     = (const float*)d_in[0];
    const float* W_in  = (const float*)d_in[1];
    const float* cw0   = (const float*)d_in[2];
    const float* cb0   = (const float*)d_in[3];
    const float* Wx0   = (const float*)d_in[4];
    const float* Wdt0  = (const float*)d_in[5];
    const float* bdt0  = (const float*)d_in[6];
    const float* Al0   = (const float*)d_in[7];
    const float* Dp0   = (const float*)d_in[8];
    const float* cw1   = (const float*)d_in[9];
    const float* cb1   = (const float*)d_in[10];
    const float* Wx1   = (const float*)d_in[11];
    const float* Wdt1  = (const float*)d_in[12];
    const float* bdt1  = (const float*)d_in[13];
    const float* Al1   = (const float*)d_in[14];
    const float* Dp1   = (const float*)d_in[15];
    const float* W_out = (const float*)d_in[16];
    float* out = (float*)d_out;

    float *p_xz, *p_xc, *p_dbc, *p_dbcp, *p_delta, *p_y;
    cudaGetSymbolAddress((void**)&p_xz,    g_xz);
    cudaGetSymbolAddress((void**)&p_xc,    g_xconv);
    cudaGetSymbolAddress((void**)&p_dbc,   g_dbc);
    cudaGetSymbolAddress((void**)&p_dbcp,  g_dbcp);
    cudaGetSymbolAddress((void**)&p_delta, g_delta);
    cudaGetSymbolAddress((void**)&p_y,     g_y);

    // 0) xz = x @ W_in.T : (2048 x 4096), K=1024
    tgemm_nt<<<dim3(2 * ED / 128, MROWS / 128, 1), 256>>>(
        x, nullptr, DM, 0, W_in, W_in, DM, p_xz, 2 * ED, 0,
        MROWS, 2 * ED, DM, DM, 1, 0, nullptr, nullptr);

    // 1) conv + silu, both dirs
    conv_silu_kernel<<<(unsigned)((2 * NED + 255) / 256), 256>>>(
        p_xz, cw0, cb0, cw1, cb1, p_xc);

    // 2) dbc partials = xconv @ Wx.T : (2048 x 96), K=2048, split-K x8, both dirs
    tgemm_nt<<<dim3(1, MROWS / 128, 2 * SPLITS), 256>>>(
        p_xc, nullptr, ED, NED, Wx0, Wx1, ED, p_dbcp, KX, (size_t)SPLITS * NDBC,
        MROWS, KX, ED, ED / SPLITS, SPLITS, 0, nullptr, nullptr);

    // 3) reduce partials
    reduce_splits<<<(unsigned)((2 * NDBC + 255) / 256), 256>>>(
        p_dbcp, p_dbc, (int)NDBC);

    // 4) delta = softplus(dbc[:, :64] @ Wdt.T + b_dt), K=64, both dirs
    tgemm_nt<<<dim3(ED / 128, MROWS / 128, 2), 256>>>(
        p_dbc, nullptr, KX, NDBC, Wdt0, Wdt1, DTR, p_delta, ED, NED,
        MROWS, ED, DTR, DTR, 1, 1, bdt0, bdt1);

    // 5) selective scan, both dirs
    scan_kernel<<<512, 128>>>(p_delta, p_xc, p_dbc, p_xz,
                              Al0, Al1, Dp0, Dp1, p_y);

    // 6) out = 0.5*(y0+y1) @ W_out.T : (2048 x 1024), K=2048
    tgemm_nt<<<dim3(DM / 128, MROWS / 128, 1), 256>>>(
        p_y, p_y + NED, ED, 0, W_out, W_out, ED, out, DM, 0,
        MROWS, DM, ED, ED, 1, 0, nullptr, nullptr);
}

// round 8
// speedup vs baseline: 2.4885x; 1.2567x over previous
#include <cuda_runtime.h>
#include <cuda_bf16.h>
#include <math.h>

#define B_SZ 4
#define LSEQ 512
#define DM   1024
#define ED   2048
#define NS   16
#define DTR  64
#define KX   96                 // DTR + 2*NS
#define MROWS (B_SZ*LSEQ)       // 2048
#define SPLITS 8
#define NED   ((size_t)MROWS * ED)
#define NDBC  ((size_t)MROWS * KX)

#define N_X    ((size_t)MROWS * DM)       // 2,097,152
#define N_WIN  ((size_t)2 * ED * DM)      // 4,194,304
#define N_WX   ((size_t)KX * ED)          // 196,608
#define N_WDT  ((size_t)ED * DTR)         // 131,072
#define N_WOUT ((size_t)DM * ED)          // 2,097,152

// ---------------- scratch (static device globals; no runtime allocation) ----
__device__ __align__(16) float g_xz   [(size_t)MROWS * 2 * ED];
__device__ __align__(16) float g_xconv[2 * NED];
__device__ __align__(16) float g_dbc  [2 * NDBC];
__device__ __align__(16) float g_dbcp [2 * (size_t)SPLITS * NDBC];
__device__ __align__(16) float g_delta[2 * NED];
__device__ __align__(16) float g_y    [2 * NED];

// bf16 hi/lo split operands
__device__ __align__(16) __nv_bfloat16 g_xh[N_X],     g_xl[N_X];
__device__ __align__(16) __nv_bfloat16 g_Winh[N_WIN], g_Winl[N_WIN];
__device__ __align__(16) __nv_bfloat16 g_Wxh[2*N_WX], g_Wxl[2*N_WX];
__device__ __align__(16) __nv_bfloat16 g_Wdth[2*N_WDT], g_Wdtl[2*N_WDT];
__device__ __align__(16) __nv_bfloat16 g_Wouth[N_WOUT], g_Woutl[N_WOUT];
__device__ __align__(16) __nv_bfloat16 g_xch[2*NED], g_xcl[2*NED];
__device__ __align__(16) __nv_bfloat16 g_dbch[2*NDBC], g_dbcl[2*NDBC];
__device__ __align__(16) __nv_bfloat16 g_ych[NED], g_ycl[NED];

__device__ __forceinline__ float sigmoidf_(float v) {
    return 1.f / (1.f + __expf(-v));
}

__device__ __forceinline__ void s1(float v, __nv_bfloat16& h, __nv_bfloat16& l) {
    h = __float2bfloat16(v);
    l = __float2bfloat16(v - __bfloat162float(h));
}

// bf16 m16n8k16 MMA (row.col), fp32 accumulate in-place.
__device__ __forceinline__ void mma_bf16(float c[4],
                                         unsigned a0, unsigned a1,
                                         unsigned a2, unsigned a3,
                                         unsigned b0, unsigned b1)
{
    asm volatile(
        "mma.sync.aligned.m16n8k16.row.col.f32.bf16.bf16.f32 "
        "{%0,%1,%2,%3}, {%4,%5,%6,%7}, {%8,%9}, {%0,%1,%2,%3};\n"
        : "+f"(c[0]), "+f"(c[1]), "+f"(c[2]), "+f"(c[3])
        : "r"(a0), "r"(a1), "r"(a2), "r"(a3), "r"(b0), "r"(b1));
}

__device__ __forceinline__ void cpa16(unsigned saddr, const void* g, bool v) {
    asm volatile("cp.async.ca.shared.global [%0], [%1], 16, %2;\n"
                 :: "r"(saddr), "l"(g), "r"(v ? 16 : 0));
}

// ---------------------------------------------------------------------------
// Tensor-core NT GEMM, pre-split bf16 (3-MMA compensated):
//   C[m,n] = sum_k (Ah+Al)[m,k] * (Bh+Bl)[n,k]  (dropping Al*Bl)
// BM=BN=128, BK=32, 256 threads = 8 warps (2x4), warp tile 64x32.
// Double-buffered cp.async staging. Smem: [row][16 kpair words], swizzle
// kp ^= ((row>>1)&3)<<2 -> conflict-free fragment LDS.
// blockIdx.z = dir*zdiv + split s. epi1 = softplus(v+bias[n]).
// ---------------------------------------------------------------------------
__global__ __launch_bounds__(256) void tgemm_bf16(
    const __nv_bfloat16* __restrict__ Ahp, const __nv_bfloat16* __restrict__ Alp,
    int lda, size_t sAdir,
    const __nv_bfloat16* __restrict__ Bh0, const __nv_bfloat16* __restrict__ Bl0,
    const __nv_bfloat16* __restrict__ Bh1, const __nv_bfloat16* __restrict__ Bl1,
    int ldb,
    float* __restrict__ C, int ldc, size_t sCdir,
    int M, int N, int Ktot, int ksz, int zdiv,
    int epi, const float* __restrict__ bias0, const float* __restrict__ bias1)
{
    extern __shared__ unsigned smem[];   // [2 buf][4 arr][2048 words] = 64KB

    const int bm  = blockIdx.y * 128;
    const int bn  = blockIdx.x * 128;
    const int dir = blockIdx.z / zdiv;
    const int s   = blockIdx.z % zdiv;
    const int k0  = s * ksz;
    int k1 = k0 + ksz; if (k1 > Ktot) k1 = Ktot;
    const int T = (k1 - k0) >> 5;        // BK=32 tiles

    const __nv_bfloat16* Ah = Ahp + (size_t)dir * sAdir;
    const __nv_bfloat16* Al = Alp + (size_t)dir * sAdir;
    const __nv_bfloat16* Bh = dir ? Bh1 : Bh0;
    const __nv_bfloat16* Bl = dir ? Bl1 : Bl0;
    const float* bias = dir ? bias1 : bias0;
    float* Cout = C + (size_t)dir * sCdir + (size_t)s * (size_t)M * (size_t)ldc;

    const int tid  = threadIdx.x;
    const int warp = tid >> 5, lane = tid & 31;
    const int wm = (warp >> 2) * 64;
    const int wn = (warp & 3) * 32;
    const int qr = lane >> 2;            // 0..7
    const int qc = lane & 3;             // 0..3

    unsigned sbase = (unsigned)__cvta_generic_to_shared(smem);

    auto stage = [&](int kbase, int buf) {
        unsigned base = sbase + buf * 32768;      // 8192 words * 4B
#pragma unroll
        for (int u = tid; u < 512; u += 256) {
            int row = u >> 2, grp = u & 3;
            int gp = grp ^ ((row >> 1) & 3);
            unsigned so = base + (unsigned)(row * 16 + gp * 4) * 4;
            const size_t ka = (size_t)(bm + row) * lda + kbase + grp * 8;
            cpa16(so,          Ah + ka, true);
            cpa16(so +  8192,  Al + ka, true);
            bool bv = (bn + row) < N;
            const size_t kb = (size_t)(bn + row) * ldb + kbase + grp * 8;
            cpa16(so + 16384,  Bh + kb, bv);
            cpa16(so + 24576,  Bl + kb, bv);
        }
        asm volatile("cp.async.commit_group;\n");
    };

    float acc[4][4][4];
#pragma unroll
    for (int i = 0; i < 4; i++)
#pragma unroll
        for (int j = 0; j < 4; j++)
#pragma unroll
            for (int r = 0; r < 4; r++) acc[i][j][r] = 0.f;

    stage(k0, 0);

    for (int t = 0; t < T; t++) {
        const int nxt = (t + 1 < T) ? t + 1 : t;
        stage(k0 + nxt * 32, (t + 1) & 1);
        asm volatile("cp.async.wait_group 1;\n");
        __syncthreads();

        const unsigned* SAh = smem + (t & 1) * 8192;
        const unsigned* SAl = SAh + 2048;
        const unsigned* SBh = SAh + 4096;
        const unsigned* SBl = SAh + 6144;

#pragma unroll
        for (int kk = 0; kk < 2; kk++) {
            const int kpb = kk * 8;
            unsigned bh0[4], bh1[4], bl0[4], bl1[4];
#pragma unroll
            for (int j = 0; j < 4; j++) {
                const int n0 = wn + j * 8 + qr;
                const int sw = ((n0 >> 1) & 3) << 2;
                const unsigned* rh = SBh + n0 * 16;
                const unsigned* rl = SBl + n0 * 16;
                bh0[j] = rh[(qc + kpb) ^ sw];
                bh1[j] = rh[(qc + 4 + kpb) ^ sw];
                bl0[j] = rl[(qc + kpb) ^ sw];
                bl1[j] = rl[(qc + 4 + kpb) ^ sw];
            }
#pragma unroll
            for (int i = 0; i < 4; i++) {
                const int r0 = wm + i * 16 + qr;
                const int r1 = r0 + 8;
                const int sw0 = ((r0 >> 1) & 3) << 2;
                const int sw1 = ((r1 >> 1) & 3) << 2;
                unsigned ah0 = SAh[r0 * 16 + ((qc + kpb) ^ sw0)];
                unsigned ah1 = SAh[r1 * 16 + ((qc + kpb) ^ sw1)];
                unsigned ah2 = SAh[r0 * 16 + ((qc + 4 + kpb) ^ sw0)];
                unsigned ah3 = SAh[r1 * 16 + ((qc + 4 + kpb) ^ sw1)];
                unsigned al0 = SAl[r0 * 16 + ((qc + kpb) ^ sw0)];
                unsigned al1 = SAl[r1 * 16 + ((qc + kpb) ^ sw1)];
                unsigned al2 = SAl[r0 * 16 + ((qc + 4 + kpb) ^ sw0)];
                unsigned al3 = SAl[r1 * 16 + ((qc + 4 + kpb) ^ sw1)];
#pragma unroll
                for (int j = 0; j < 4; j++) {
                    mma_bf16(acc[i][j], ah0, ah1, ah2, ah3, bh0[j], bh1[j]);
                    mma_bf16(acc[i][j], al0, al1, al2, al3, bh0[j], bh1[j]);
                    mma_bf16(acc[i][j], ah0, ah1, ah2, ah3, bl0[j], bl1[j]);
                }
            }
        }
        __syncthreads();
    }

#pragma unroll
    for (int i = 0; i < 4; i++) {
        const int row0 = bm + wm + i * 16 + qr;
#pragma unroll
        for (int j = 0; j < 4; j++) {
            const int cc = bn + wn + j * 8 + qc * 2;
            if (cc < N) {
#pragma unroll
                for (int half = 0; half < 2; half++) {
                    const int rr = row0 + half * 8;
                    float v0 = acc[i][j][half * 2];
                    float v1 = acc[i][j][half * 2 + 1];
                    if (epi == 1) {
                        v0 += bias[cc];
                        v1 += bias[cc + 1];
                        v0 = (v0 > 15.f) ? v0 : __logf(1.f + __expf(v0));
                        v1 = (v1 > 15.f) ? v1 : __logf(1.f + __expf(v1));
                    }
                    *reinterpret_cast<float2*>(&Cout[(size_t)rr * ldc + cc]) =
                        make_float2(v0, v1);
                }
            }
        }
    }
}

// ---------------------------------------------------------------------------
// One-shot split of x + all weights into bf16 hi/lo. 4 elems per thread.
// ---------------------------------------------------------------------------
__global__ __launch_bounds__(256) void split_all(
    const float* __restrict__ x,   const float* __restrict__ Win,
    const float* __restrict__ Wx0, const float* __restrict__ Wx1,
    const float* __restrict__ Wdt0,const float* __restrict__ Wdt1,
    const float* __restrict__ Wout)
{
    const size_t O0 = 0;
    const size_t O1 = O0 + N_X;
    const size_t O2 = O1 + N_WIN;
    const size_t O3 = O2 + N_WX;
    const size_t O4 = O3 + N_WX;
    const size_t O5 = O4 + N_WDT;
    const size_t O6 = O5 + N_WDT;
    const size_t O7 = O6 + N_WOUT;

    size_t i = ((size_t)blockIdx.x * 256 + threadIdx.x) * 4;
    if (i >= O7) return;

    const float* src; __nv_bfloat16 *ph, *pl; size_t off;
    if      (i < O1) { src = x;    ph = g_xh;            pl = g_xl;            off = O0; }
    else if (i < O2) { src = Win;  ph = g_Winh;          pl = g_Winl;          off = O1; }
    else if (i < O3) { src = Wx0;  ph = g_Wxh;           pl = g_Wxl;           off = O2; }
    else if (i < O4) { src = Wx1;  ph = g_Wxh + N_WX;    pl = g_Wxl + N_WX;    off = O3; }
    else if (i < O5) { src = Wdt0; ph = g_Wdth;          pl = g_Wdtl;          off = O4; }
    else if (i < O6) { src = Wdt1; ph = g_Wdth + N_WDT;  pl = g_Wdtl + N_WDT;  off = O5; }
    else             { src = Wout; ph = g_Wouth;         pl = g_Woutl;         off = O6; }

    size_t k = i - off;
    float4 v = *reinterpret_cast<const float4*>(src + k);
    __nv_bfloat16 h[4], l[4];
    s1(v.x, h[0], l[0]); s1(v.y, h[1], l[1]);
    s1(v.z, h[2], l[2]); s1(v.w, h[3], l[3]);
    *reinterpret_cast<uint2*>(ph + k) = *reinterpret_cast<uint2*>(h);
    *reinterpret_cast<uint2*>(pl + k) = *reinterpret_cast<uint2*>(l);
}

// ---------------------------------------------------------------------------
// Reduce split-K partials for both dirs + bf16 split of result.
// ---------------------------------------------------------------------------
__global__ void reduce_splits(const float* __restrict__ part,
                              float* __restrict__ outp, int n1)
{
    int i = blockIdx.x * blockDim.x + threadIdx.x;
    if (i >= 2 * n1) return;
    int dir = i / n1, ii = i - dir * n1;
    const float* p = part + (size_t)dir * SPLITS * n1;
    float s = 0.f;
#pragma unroll
    for (int j = 0; j < SPLITS; j++) s += p[(size_t)j * n1 + ii];
    outp[i] = s;
    s1(s, g_dbch[i], g_dbcl[i]);
}

// ---------------------------------------------------------------------------
// Causal depthwise conv (K=4) + SiLU, both dirs; writes fp32 + bf16 hi/lo.
// ---------------------------------------------------------------------------
__global__ __launch_bounds__(256) void conv_silu_kernel(
    const float* __restrict__ xz,
    const float* __restrict__ w0, const float* __restrict__ cb0,
    const float* __restrict__ w1, const float* __restrict__ cb1,
    float* __restrict__ xc)
{
    size_t idx = (size_t)blockIdx.x * blockDim.x + threadIdx.x;
    if (idx >= 2 * NED) return;
    const int dir = (int)(idx / NED);
    size_t loc = idx - (size_t)dir * NED;
    int e = (int)(loc % ED);
    int t = (int)((loc / ED) % LSEQ);
    int b = (int)(loc / ((size_t)ED * LSEQ));
    const float* w  = dir ? w1  : w0;
    const float* cb = dir ? cb1 : cb0;

    float acc = cb[e];
#pragma unroll
    for (int i = 0; i < 4; i++) {
        int tau = t - 3 + i;
        if (tau >= 0) {
            int tt = dir ? (LSEQ - 1 - tau) : tau;
            acc = fmaf(w[e * 4 + i],
                       xz[((size_t)b * LSEQ + tt) * (2 * ED) + e], acc);
        }
    }
    float val = acc * sigmoidf_(acc);
    xc[idx] = val;
    s1(val, g_xch[idx], g_xcl[idx]);
}

// ---------------------------------------------------------------------------
// Combine y = 0.5*(y0+y1) and split to bf16 hi/lo for the output GEMM.
// ---------------------------------------------------------------------------
__global__ __launch_bounds__(256) void combine_kernel(
    const float* __restrict__ y)
{
    size_t i = ((size_t)blockIdx.x * 256 + threadIdx.x) * 4;
    if (i >= NED) return;
    float4 a = *reinterpret_cast<const float4*>(y + i);
    float4 b = *reinterpret_cast<const float4*>(y + NED + i);
    __nv_bfloat16 h[4], l[4];
    s1(0.5f * (a.x + b.x), h[0], l[0]);
    s1(0.5f * (a.y + b.y), h[1], l[1]);
    s1(0.5f * (a.z + b.z), h[2], l[2]);
    s1(0.5f * (a.w + b.w), h[3], l[3]);
    *reinterpret_cast<uint2*>(g_ych + i) = *reinterpret_cast<uint2*>(h);
    *reinterpret_cast<uint2*>(g_ycl + i) = *reinterpret_cast<uint2*>(l);
}

// ---------------------------------------------------------------------------
// Selective scan, both directions in one launch (512 blocks x 128 threads).
// ---------------------------------------------------------------------------
__global__ __launch_bounds__(128) void scan_kernel(
    const float* __restrict__ delta,
    const float* __restrict__ xconv,
    const float* __restrict__ dbc,
    const float* __restrict__ xz,
    const float* __restrict__ A0, const float* __restrict__ A1,
    const float* __restrict__ D0, const float* __restrict__ D1,
    float* __restrict__ y)
{
    const int dir = blockIdx.x >> 8;
    const int rb  = blockIdx.x & 255;
    const int b   = rb >> 6;
    const int ec  = rb & 63;
    const int tid = threadIdx.x;
    const int e = ec * 32 + (tid >> 2);
    const int g = tid & 3;

    const float* dlt  = delta + (size_t)dir * NED;
    const float* xcv  = xconv + (size_t)dir * NED;
    const float* dbcd = dbc + (size_t)dir * NDBC;
    const float* A_log = dir ? A1 : A0;
    const float* Dp    = dir ? D1 : D0;
    float* yo = y + (size_t)dir * NED;

    float4 al = *reinterpret_cast<const float4*>(&A_log[e * NS + g * 4]);
    const float Aa = -__expf(al.x), Ab = -__expf(al.y),
                Ac = -__expf(al.z), Ad = -__expf(al.w);
    const float dp = Dp[e];

    float h0 = 0.f, h1 = 0.f, h2 = 0.f, h3 = 0.f;
    const size_t baseBL = (size_t)b * LSEQ;

    for (int t = 0; t < LSEQ; t++) {
        const size_t row = baseBL + t;
        const float d  = dlt[row * ED + e];
        const float xv = xcv[row * ED + e];
        const int   tt = dir ? (LSEQ - 1 - t) : t;
        const float zv = xz[(baseBL + tt) * (2 * ED) + ED + e];
        float4 Bv = *reinterpret_cast<const float4*>(&dbcd[row * KX + DTR + g * 4]);
        float4 Cv = *reinterpret_cast<const float4*>(&dbcd[row * KX + DTR + NS + g * 4]);

        const float dx = d * xv;
        h0 = fmaf(__expf(d * Aa), h0, dx * Bv.x);
        h1 = fmaf(__expf(d * Ab), h1, dx * Bv.y);
        h2 = fmaf(__expf(d * Ac), h2, dx * Bv.z);
        h3 = fmaf(__expf(d * Ad), h3, dx * Bv.w);

        float yp = h0 * Cv.x + h1 * Cv.y + h2 * Cv.z + h3 * Cv.w;
        yp += __shfl_xor_sync(0xffffffffu, yp, 1);
        yp += __shfl_xor_sync(0xffffffffu, yp, 2);

        if (g == 0) {
            float yt  = yp + dp * xv;
            float val = yt * (zv * sigmoidf_(zv));
            size_t orow = dir ? (baseBL + (LSEQ - 1 - t)) : row;
            yo[orow * ED + e] = val;
        }
    }
}

// ---------------------------------------------------------------------------
extern "C" void kernel_launch(void* const* d_in, const int* in_sizes, int n_in,
                              void* d_out, int out_size)
{
    (void)in_sizes; (void)n_in; (void)out_size;
    const float* x     = (const float*)d_in[0];
    const float* W_in  = (const float*)d_in[1];
    const float* cw0   = (const float*)d_in[2];
    const float* cb0   = (const float*)d_in[3];
    const float* Wx0   = (const float*)d_in[4];
    const float* Wdt0  = (const float*)d_in[5];
    const float* bdt0  = (const float*)d_in[6];
    const float* Al0   = (const float*)d_in[7];
    const float* Dp0   = (const float*)d_in[8];
    const float* cw1   = (const float*)d_in[9];
    const float* cb1   = (const float*)d_in[10];
    const float* Wx1   = (const float*)d_in[11];
    const float* Wdt1  = (const float*)d_in[12];
    const float* bdt1  = (const float*)d_in[13];
    const float* Al1   = (const float*)d_in[14];
    const float* Dp1   = (const float*)d_in[15];
    const float* W_out = (const float*)d_in[16];
    float* out = (float*)d_out;

    static int smem_set = 0;
    cudaFuncSetAttribute(tgemm_bf16,
                         cudaFuncAttributeMaxDynamicSharedMemorySize, 65536);
    (void)smem_set;

    float *p_xz, *p_xc, *p_dbc, *p_dbcp, *p_delta, *p_y;
    cudaGetSymbolAddress((void**)&p_xz,    g_xz);
    cudaGetSymbolAddress((void**)&p_xc,    g_xconv);
    cudaGetSymbolAddress((void**)&p_dbc,   g_dbc);
    cudaGetSymbolAddress((void**)&p_dbcp,  g_dbcp);
    cudaGetSymbolAddress((void**)&p_delta, g_delta);
    cudaGetSymbolAddress((void**)&p_y,     g_y);

    __nv_bfloat16 *xh, *xl, *Winh, *Winl, *Wxh, *Wxl, *Wdth, *Wdtl;
    __nv_bfloat16 *Wouth, *Woutl, *xch, *xcl, *dbch, *dbcl, *ych, *ycl;
    cudaGetSymbolAddress((void**)&xh,    g_xh);
    cudaGetSymbolAddress((void**)&xl,    g_xl);
    cudaGetSymbolAddress((void**)&Winh,  g_Winh);
    cudaGetSymbolAddress((void**)&Winl,  g_Winl);
    cudaGetSymbolAddress((void**)&Wxh,   g_Wxh);
    cudaGetSymbolAddress((void**)&Wxl,   g_Wxl);
    cudaGetSymbolAddress((void**)&Wdth,  g_Wdth);
    cudaGetSymbolAddress((void**)&Wdtl,  g_Wdtl);
    cudaGetSymbolAddress((void**)&Wouth, g_Wouth);
    cudaGetSymbolAddress((void**)&Woutl, g_Woutl);
    cudaGetSymbolAddress((void**)&xch,   g_xch);
    cudaGetSymbolAddress((void**)&xcl,   g_xcl);
    cudaGetSymbolAddress((void**)&dbch,  g_dbch);
    cudaGetSymbolAddress((void**)&dbcl,  g_dbcl);
    cudaGetSymbolAddress((void**)&ych,   g_ych);
    cudaGetSymbolAddress((void**)&ycl,   g_ycl);

    // A) one-shot split of x + all weights
    const size_t tot4 = (N_X + N_WIN + 2*N_WX + 2*N_WDT + N_WOUT) / 4;
    split_all<<<(unsigned)((tot4 + 255) / 256), 256>>>(
        x, W_in, Wx0, Wx1, Wdt0, Wdt1, W_out);

    // 0) xz = x @ W_in.T : (2048 x 4096), K=1024
    tgemm_bf16<<<dim3(2 * ED / 128, MROWS / 128, 1), 256, 65536>>>(
        xh, xl, DM, 0, Winh, Winl, Winh, Winl, DM,
        p_xz, 2 * ED, 0, MROWS, 2 * ED, DM, DM, 1, 0, nullptr, nullptr);

    // 1) conv + silu (writes fp32 + bf16 hi/lo), both dirs
    conv_silu_kernel<<<(unsigned)((2 * NED + 255) / 256), 256>>>(
        p_xz, cw0, cb0, cw1, cb1, p_xc);

    // 2) dbc partials = xconv @ Wx.T : (2048 x 96), K=2048, split-K x8, both dirs
    tgemm_bf16<<<dim3(1, MROWS / 128, 2 * SPLITS), 256, 65536>>>(
        xch, xcl, ED, NED, Wxh, Wxl, Wxh + N_WX, Wxl + N_WX, ED,
        p_dbcp, KX, (size_t)SPLITS * NDBC,
        MROWS, KX, ED, ED / SPLITS, SPLITS, 0, nullptr, nullptr);

    // 3) reduce partials (+ bf16 split)
    reduce_splits<<<(unsigned)((2 * NDBC + 255) / 256), 256>>>(
        p_dbcp, p_dbc, (int)NDBC);

    // 4) delta = softplus(dbc[:, :64] @ Wdt.T + b_dt), K=64, both dirs
    tgemm_bf16<<<dim3(ED / 128, MROWS / 128, 2), 256, 65536>>>(
        dbch, dbcl, KX, NDBC, Wdth, Wdtl, Wdth + N_WDT, Wdtl + N_WDT, DTR,
        p_delta, ED, NED, MROWS, ED, DTR, DTR, 1, 1, bdt0, bdt1);

    // 5) selective scan, both dirs
    scan_kernel<<<512, 128>>>(p_delta, p_xc, p_dbc, p_xz,
                              Al0, Al1, Dp0, Dp1, p_y);

    // 6) combine y = 0.5*(y0+y1) -> bf16 hi/lo
    combine_kernel<<<(unsigned)((NED / 4 + 255) / 256), 256>>>(p_y);

    // 7) out = yc @ W_out.T : (2048 x 1024), K=2048
    tgemm_bf16<<<dim3(DM / 128, MROWS / 128, 1), 256, 65536>>>(
        ych, ycl, ED, 0, Wouth, Woutl, Wouth, Woutl, ED,
        out, DM, 0, MROWS, DM, ED, ED, 1, 0, nullptr, nullptr);
}

// round 11
// speedup vs baseline: 2.5055x; 1.0068x over previous
#include <cuda_runtime.h>
#include <cuda_bf16.h>
#include <math.h>

#define B_SZ 4
#define LSEQ 512
#define DM   1024
#define ED   2048
#define NS   16
#define DTR  64
#define KX   96                 // DTR + 2*NS
#define MROWS (B_SZ*LSEQ)       // 2048
#define SPLITS 8
#define NED   ((size_t)MROWS * ED)
#define NDBC  ((size_t)MROWS * KX)

#define N_X    ((size_t)MROWS * DM)
#define N_WIN  ((size_t)2 * ED * DM)
#define N_WX   ((size_t)KX * ED)
#define N_WDT  ((size_t)ED * DTR)
#define N_WOUT ((size_t)DM * ED)

// ---------------- scratch (static device globals; no runtime allocation) ----
__device__ __align__(16) float g_xz   [(size_t)MROWS * 2 * ED];
__device__ __align__(16) float g_xconv[2 * NED];
__device__ __align__(16) float g_dbc  [2 * NDBC];
__device__ __align__(16) float g_dbcp [2 * (size_t)SPLITS * NDBC];
__device__ __align__(16) float g_delta[2 * NED];
__device__ __align__(16) float g_y    [2 * NED];

// bf16 hi/lo split operands
__device__ __align__(16) __nv_bfloat16 g_xh[N_X],     g_xl[N_X];
__device__ __align__(16) __nv_bfloat16 g_Winh[N_WIN], g_Winl[N_WIN];
__device__ __align__(16) __nv_bfloat16 g_Wxh[2*N_WX], g_Wxl[2*N_WX];
__device__ __align__(16) __nv_bfloat16 g_Wdth[2*N_WDT], g_Wdtl[2*N_WDT];
__device__ __align__(16) __nv_bfloat16 g_Wouth[N_WOUT], g_Woutl[N_WOUT];
__device__ __align__(16) __nv_bfloat16 g_xch[2*NED], g_xcl[2*NED];
__device__ __align__(16) __nv_bfloat16 g_dbch[2*NDBC], g_dbcl[2*NDBC];
__device__ __align__(16) __nv_bfloat16 g_ych[NED], g_ycl[NED];

__device__ __forceinline__ float sigmoidf_(float v) {
    return 1.f / (1.f + __expf(-v));
}

__device__ __forceinline__ void s1(float v, __nv_bfloat16& h, __nv_bfloat16& l) {
    h = __float2bfloat16(v);
    l = __float2bfloat16(v - __bfloat162float(h));
}

// bf16 m16n8k16 MMA (row.col), fp32 accumulate in-place.
__device__ __forceinline__ void mma_bf16(float c[4],
                                         unsigned a0, unsigned a1,
                                         unsigned a2, unsigned a3,
                                         unsigned b0, unsigned b1)
{
    asm volatile(
        "mma.sync.aligned.m16n8k16.row.col.f32.bf16.bf16.f32 "
        "{%0,%1,%2,%3}, {%4,%5,%6,%7}, {%8,%9}, {%0,%1,%2,%3};\n"
        : "+f"(c[0]), "+f"(c[1]), "+f"(c[2]), "+f"(c[3])
        : "r"(a0), "r"(a1), "r"(a2), "r"(a3), "r"(b0), "r"(b1));
}

__device__ __forceinline__ void ldsm_x4(unsigned& r0, unsigned& r1,
                                        unsigned& r2, unsigned& r3, unsigned a)
{
    asm volatile("ldmatrix.sync.aligned.m8n8.x4.shared.b16 {%0,%1,%2,%3}, [%4];"
                 : "=r"(r0), "=r"(r1), "=r"(r2), "=r"(r3) : "r"(a));
}

__device__ __forceinline__ void ldsm_x2(unsigned& r0, unsigned& r1, unsigned a)
{
    asm volatile("ldmatrix.sync.aligned.m8n8.x2.shared.b16 {%0,%1}, [%2];"
                 : "=r"(r0), "=r"(r1) : "r"(a));
}

__device__ __forceinline__ void cpa16(unsigned saddr, const void* g, bool v) {
    asm volatile("cp.async.ca.shared.global [%0], [%1], 16, %2;\n"
                 :: "r"(saddr), "l"(g), "r"(v ? 16 : 0));
}

// ---------------------------------------------------------------------------
// Tensor-core NT GEMM, pre-split bf16 (3-MMA compensated):
//   C[m,n] = sum_k (Ah+Al)[m,k] * (Bh+Bl)[n,k]  (dropping Al*Bl)
// BM=BN=128, BK=32, 256 threads = 8 warps (2x4), warp tile 64x32.
// Double-buffered cp.async staging; ldmatrix fragment loads.
// Smem layout: per buffer [Ah 8K | Al 8K | Bh 8K | Bl 8K] bytes; row = 64B
// (32 bf16), stored as 4 16B-chunks swizzled chunk ^= (row>>1)&3.
// blockIdx.z = dir*zdiv + split s. epi1 = softplus(v+bias[n]).
// ---------------------------------------------------------------------------
__global__ __launch_bounds__(256) void tgemm_bf16(
    const __nv_bfloat16* __restrict__ Ahp, const __nv_bfloat16* __restrict__ Alp,
    int lda, size_t sAdir,
    const __nv_bfloat16* __restrict__ Bh0, const __nv_bfloat16* __restrict__ Bl0,
    const __nv_bfloat16* __restrict__ Bh1, const __nv_bfloat16* __restrict__ Bl1,
    int ldb,
    float* __restrict__ C, int ldc, size_t sCdir,
    int M, int N, int Ktot, int ksz, int zdiv,
    int epi, const float* __restrict__ bias0, const float* __restrict__ bias1)
{
    extern __shared__ unsigned smem[];   // 2 x 32KB

    const int bm  = blockIdx.y * 128;
    const int bn  = blockIdx.x * 128;
    const int dir = blockIdx.z / zdiv;
    const int s   = blockIdx.z % zdiv;
    const int k0  = s * ksz;
    int k1 = k0 + ksz; if (k1 > Ktot) k1 = Ktot;
    const int T = (k1 - k0) >> 5;        // BK=32 tiles

    const __nv_bfloat16* Ah = Ahp + (size_t)dir * sAdir;
    const __nv_bfloat16* Al = Alp + (size_t)dir * sAdir;
    const __nv_bfloat16* Bh = dir ? Bh1 : Bh0;
    const __nv_bfloat16* Bl = dir ? Bl1 : Bl0;
    const float* bias = dir ? bias1 : bias0;
    float* Cout = C + (size_t)dir * sCdir + (size_t)s * (size_t)M * (size_t)ldc;

    const int tid  = threadIdx.x;
    const int warp = tid >> 5, lane = tid & 31;
    const int wm = (warp >> 2) * 64;
    const int wn = (warp & 3) * 32;
    const int qr = lane >> 2;            // 0..7
    const int qc = lane & 3;             // 0..3

    unsigned sbase = (unsigned)__cvta_generic_to_shared(smem);

    auto stage = [&](int kbase, int buf) {
        unsigned base = sbase + buf * 32768;
#pragma unroll
        for (int u = tid; u < 512; u += 256) {
            int row = u >> 2, grp = u & 3;
            int gp = grp ^ ((row >> 1) & 3);
            unsigned so = base + (unsigned)(row * 64 + gp * 16);
            const size_t ka = (size_t)(bm + row) * lda + kbase + grp * 8;
            cpa16(so,          Ah + ka, true);
            cpa16(so +  8192,  Al + ka, true);
            bool bv = (bn + row) < N;
            const size_t kb = (size_t)(bn + row) * ldb + kbase + grp * 8;
            cpa16(so + 16384,  Bh + kb, bv);
            cpa16(so + 24576,  Bl + kb, bv);
        }
        asm volatile("cp.async.commit_group;\n");
    };

    // precomputed ldmatrix byte offsets (within one operand array, kk=0)
    unsigned aoff[4], boff[4];
#pragma unroll
    for (int i = 0; i < 4; i++) {
        int row = wm + i * 16 + (lane & 15);
        int ch  = lane >> 4;                      // 0: k0-7, 1: k8-15
        int g   = ch ^ ((row >> 1) & 3);
        aoff[i] = (unsigned)(row * 64 + g * 16);
    }
#pragma unroll
    for (int j = 0; j < 4; j++) {
        int row = wn + j * 8 + (lane & 7);
        int ch  = (lane >> 3) & 1;
        int g   = ch ^ ((row >> 1) & 3);
        boff[j] = (unsigned)(row * 64 + g * 16);
    }

    float acc[4][4][4];
#pragma unroll
    for (int i = 0; i < 4; i++)
#pragma unroll
        for (int j = 0; j < 4; j++)
#pragma unroll
            for (int r = 0; r < 4; r++) acc[i][j][r] = 0.f;

    stage(k0, 0);

    for (int t = 0; t < T; t++) {
        const int nxt = (t + 1 < T) ? t + 1 : t;
        stage(k0 + nxt * 32, (t + 1) & 1);
        asm volatile("cp.async.wait_group 1;\n");
        __syncthreads();

        const unsigned Ab = sbase + (t & 1) * 32768;

#pragma unroll
        for (int kk = 0; kk < 2; kk++) {
            const unsigned kx = kk * 32;          // chunk 0/1 -> 2/3 via XOR
            unsigned bh0[4], bh1[4], bl0[4], bl1[4];
#pragma unroll
            for (int j = 0; j < 4; j++) {
                ldsm_x2(bh0[j], bh1[j], Ab + 16384 + (boff[j] ^ kx));
                ldsm_x2(bl0[j], bl1[j], Ab + 24576 + (boff[j] ^ kx));
            }
#pragma unroll
            for (int i = 0; i < 4; i++) {
                unsigned ah0, ah1, ah2, ah3, al0, al1, al2, al3;
                ldsm_x4(ah0, ah1, ah2, ah3, Ab + (aoff[i] ^ kx));
                ldsm_x4(al0, al1, al2, al3, Ab + 8192 + (aoff[i] ^ kx));
#pragma unroll
                for (int j = 0; j < 4; j++) {
                    mma_bf16(acc[i][j], ah0, ah1, ah2, ah3, bh0[j], bh1[j]);
                    mma_bf16(acc[i][j], al0, al1, al2, al3, bh0[j], bh1[j]);
                    mma_bf16(acc[i][j], ah0, ah1, ah2, ah3, bl0[j], bl1[j]);
                }
            }
        }
        __syncthreads();
    }

    // epilogue: (c0,c1)=(qr,2qc..2qc+1), (c2,c3)=(qr+8,..) -> float2 stores
#pragma unroll
    for (int i = 0; i < 4; i++) {
        const int row0 = bm + wm + i * 16 + qr;
#pragma unroll
        for (int j = 0; j < 4; j++) {
            const int cc = bn + wn + j * 8 + qc * 2;
            if (cc < N) {
#pragma unroll
                for (int half = 0; half < 2; half++) {
                    const int rr = row0 + half * 8;
                    float v0 = acc[i][j][half * 2];
                    float v1 = acc[i][j][half * 2 + 1];
                    if (epi == 1) {
                        v0 += bias[cc];
                        v1 += bias[cc + 1];
                        v0 = (v0 > 15.f) ? v0 : __logf(1.f + __expf(v0));
                        v1 = (v1 > 15.f) ? v1 : __logf(1.f + __expf(v1));
                    }
                    *reinterpret_cast<float2*>(&Cout[(size_t)rr * ldc + cc]) =
                        make_float2(v0, v1);
                }
            }
        }
    }
}

// ---------------------------------------------------------------------------
// One-shot split of x + all weights into bf16 hi/lo. 4 elems per thread.
// ---------------------------------------------------------------------------
__global__ __launch_bounds__(256) void split_all(
    const float* __restrict__ x,   const float* __restrict__ Win,
    const float* __restrict__ Wx0, const float* __restrict__ Wx1,
    const float* __restrict__ Wdt0,const float* __restrict__ Wdt1,
    const float* __restrict__ Wout)
{
    const size_t O0 = 0;
    const size_t O1 = O0 + N_X;
    const size_t O2 = O1 + N_WIN;
    const size_t O3 = O2 + N_WX;
    const size_t O4 = O3 + N_WX;
    const size_t O5 = O4 + N_WDT;
    const size_t O6 = O5 + N_WDT;
    const size_t O7 = O6 + N_WOUT;

    size_t i = ((size_t)blockIdx.x * 256 + threadIdx.x) * 4;
    if (i >= O7) return;

    const float* src; __nv_bfloat16 *ph, *pl; size_t off;
    if      (i < O1) { src = x;    ph = g_xh;            pl = g_xl;            off = O0; }
    else if (i < O2) { src = Win;  ph = g_Winh;          pl = g_Winl;          off = O1; }
    else if (i < O3) { src = Wx0;  ph = g_Wxh;           pl = g_Wxl;           off = O2; }
    else if (i < O4) { src = Wx1;  ph = g_Wxh + N_WX;    pl = g_Wxl + N_WX;    off = O3; }
    else if (i < O5) { src = Wdt0; ph = g_Wdth;          pl = g_Wdtl;          off = O4; }
    else if (i < O6) { src = Wdt1; ph = g_Wdth + N_WDT;  pl = g_Wdtl + N_WDT;  off = O5; }
    else             { src = Wout; ph = g_Wouth;         pl = g_Woutl;         off = O6; }

    size_t k = i - off;
    float4 v = *reinterpret_cast<const float4*>(src + k);
    __nv_bfloat16 h[4], l[4];
    s1(v.x, h[0], l[0]); s1(v.y, h[1], l[1]);
    s1(v.z, h[2], l[2]); s1(v.w, h[3], l[3]);
    *reinterpret_cast<uint2*>(ph + k) = *reinterpret_cast<uint2*>(h);
    *reinterpret_cast<uint2*>(pl + k) = *reinterpret_cast<uint2*>(l);
}

// ---------------------------------------------------------------------------
// Reduce split-K partials for both dirs + bf16 split of result.
// ---------------------------------------------------------------------------
__global__ void reduce_splits(const float* __restrict__ part,
                              float* __restrict__ outp, int n1)
{
    int i = blockIdx.x * blockDim.x + threadIdx.x;
    if (i >= 2 * n1) return;
    int dir = i / n1, ii = i - dir * n1;
    const float* p = part + (size_t)dir * SPLITS * n1;
    float s = 0.f;
#pragma unroll
    for (int j = 0; j < SPLITS; j++) s += p[(size_t)j * n1 + ii];
    outp[i] = s;
    s1(s, g_dbch[i], g_dbcl[i]);
}

// ---------------------------------------------------------------------------
// Causal depthwise conv (K=4) + SiLU, both dirs; writes fp32 + bf16 hi/lo.
// ---------------------------------------------------------------------------
__global__ __launch_bounds__(256) void conv_silu_kernel(
    const float* __restrict__ xz,
    const float* __restrict__ w0, const float* __restrict__ cb0,
    const float* __restrict__ w1, const float* __restrict__ cb1,
    float* __restrict__ xc)
{
    size_t idx = (size_t)blockIdx.x * blockDim.x + threadIdx.x;
    if (idx >= 2 * NED) return;
    const int dir = (int)(idx / NED);
    size_t loc = idx - (size_t)dir * NED;
    int e = (int)(loc % ED);
    int t = (int)((loc / ED) % LSEQ);
    int b = (int)(loc / ((size_t)ED * LSEQ));
    const float* w  = dir ? w1  : w0;
    const float* cb = dir ? cb1 : cb0;

    float acc = cb[e];
#pragma unroll
    for (int i = 0; i < 4; i++) {
        int tau = t - 3 + i;
        if (tau >= 0) {
            int tt = dir ? (LSEQ - 1 - tau) : tau;
            acc = fmaf(w[e * 4 + i],
                       xz[((size_t)b * LSEQ + tt) * (2 * ED) + e], acc);
        }
    }
    float val = acc * sigmoidf_(acc);
    xc[idx] = val;
    s1(val, g_xch[idx], g_xcl[idx]);
}

// ---------------------------------------------------------------------------
// Combine y = 0.5*(y0+y1) and split to bf16 hi/lo for the output GEMM.
// ---------------------------------------------------------------------------
__global__ __launch_bounds__(256) void combine_kernel(
    const float* __restrict__ y)
{
    size_t i = ((size_t)blockIdx.x * 256 + threadIdx.x) * 4;
    if (i >= NED) return;
    float4 a = *reinterpret_cast<const float4*>(y + i);
    float4 b = *reinterpret_cast<const float4*>(y + NED + i);
    __nv_bfloat16 h[4], l[4];
    s1(0.5f * (a.x + b.x), h[0], l[0]);
    s1(0.5f * (a.y + b.y), h[1], l[1]);
    s1(0.5f * (a.z + b.z), h[2], l[2]);
    s1(0.5f * (a.w + b.w), h[3], l[3]);
    *reinterpret_cast<uint2*>(g_ych + i) = *reinterpret_cast<uint2*>(h);
    *reinterpret_cast<uint2*>(g_ycl + i) = *reinterpret_cast<uint2*>(l);
}

// ---------------------------------------------------------------------------
// Selective scan, both directions in one launch (512 blocks x 128 threads).
// ---------------------------------------------------------------------------
__global__ __launch_bounds__(128) void scan_kernel(
    const float* __restrict__ delta,
    const float* __restrict__ xconv,
    const float* __restrict__ dbc,
    const float* __restrict__ xz,
    const float* __restrict__ A0, const float* __restrict__ A1,
    const float* __restrict__ D0, const float* __restrict__ D1,
    float* __restrict__ y)
{
    const int dir = blockIdx.x >> 8;
    const int rb  = blockIdx.x & 255;
    const int b   = rb >> 6;
    const int ec  = rb & 63;
    const int tid = threadIdx.x;
    const int e = ec * 32 + (tid >> 2);
    const int g = tid & 3;

    const float* dlt  = delta + (size_t)dir * NED;
    const float* xcv  = xconv + (size_t)dir * NED;
    const float* dbcd = dbc + (size_t)dir * NDBC;
    const float* A_log = dir ? A1 : A0;
    const float* Dp    = dir ? D1 : D0;
    float* yo = y + (size_t)dir * NED;

    float4 al = *reinterpret_cast<const float4*>(&A_log[e * NS + g * 4]);
    const float Aa = -__expf(al.x), Ab = -__expf(al.y),
                Ac = -__expf(al.z), Ad = -__expf(al.w);
    const float dp = Dp[e];

    float h0 = 0.f, h1 = 0.f, h2 = 0.f, h3 = 0.f;
    const size_t baseBL = (size_t)b * LSEQ;

    for (int t = 0; t < LSEQ; t++) {
        const size_t row = baseBL + t;
        const float d  = dlt[row * ED + e];
        const float xv = xcv[row * ED + e];
        const int   tt = dir ? (LSEQ - 1 - t) : t;
        const float zv = xz[(baseBL + tt) * (2 * ED) + ED + e];
        float4 Bv = *reinterpret_cast<const float4*>(&dbcd[row * KX + DTR + g * 4]);
        float4 Cv = *reinterpret_cast<const float4*>(&dbcd[row * KX + DTR + NS + g * 4]);

        const float dx = d * xv;
        h0 = fmaf(__expf(d * Aa), h0, dx * Bv.x);
        h1 = fmaf(__expf(d * Ab), h1, dx * Bv.y);
        h2 = fmaf(__expf(d * Ac), h2, dx * Bv.z);
        h3 = fmaf(__expf(d * Ad), h3, dx * Bv.w);

        float yp = h0 * Cv.x + h1 * Cv.y + h2 * Cv.z + h3 * Cv.w;
        yp += __shfl_xor_sync(0xffffffffu, yp, 1);
        yp += __shfl_xor_sync(0xffffffffu, yp, 2);

        if (g == 0) {
            float yt  = yp + dp * xv;
            float val = yt * (zv * sigmoidf_(zv));
            size_t orow = dir ? (baseBL + (LSEQ - 1 - t)) : row;
            yo[orow * ED + e] = val;
        }
    }
}

// ---------------------------------------------------------------------------
extern "C" void kernel_launch(void* const* d_in, const int* in_sizes, int n_in,
                              void* d_out, int out_size)
{
    (void)in_sizes; (void)n_in; (void)out_size;
    const float* x     = (const float*)d_in[0];
    const float* W_in  = (const float*)d_in[1];
    const float* cw0   = (const float*)d_in[2];
    const float* cb0   = (const float*)d_in[3];
    const float* Wx0   = (const float*)d_in[4];
    const float* Wdt0  = (const float*)d_in[5];
    const float* bdt0  = (const float*)d_in[6];
    const float* Al0   = (const float*)d_in[7];
    const float* Dp0   = (const float*)d_in[8];
    const float* cw1   = (const float*)d_in[9];
    const float* cb1   = (const float*)d_in[10];
    const float* Wx1   = (const float*)d_in[11];
    const float* Wdt1  = (const float*)d_in[12];
    const float* bdt1  = (const float*)d_in[13];
    const float* Al1   = (const float*)d_in[14];
    const float* Dp1   = (const float*)d_in[15];
    const float* W_out = (const float*)d_in[16];
    float* out = (float*)d_out;

    cudaFuncSetAttribute(tgemm_bf16,
                         cudaFuncAttributeMaxDynamicSharedMemorySize, 65536);

    float *p_xz, *p_xc, *p_dbc, *p_dbcp, *p_delta, *p_y;
    cudaGetSymbolAddress((void**)&p_xz,    g_xz);
    cudaGetSymbolAddress((void**)&p_xc,    g_xconv);
    cudaGetSymbolAddress((void**)&p_dbc,   g_dbc);
    cudaGetSymbolAddress((void**)&p_dbcp,  g_dbcp);
    cudaGetSymbolAddress((void**)&p_delta, g_delta);
    cudaGetSymbolAddress((void**)&p_y,     g_y);

    __nv_bfloat16 *xh, *xl, *Winh, *Winl, *Wxh, *Wxl, *Wdth, *Wdtl;
    __nv_bfloat16 *Wouth, *Woutl, *xch, *xcl, *dbch, *dbcl, *ych, *ycl;
    cudaGetSymbolAddress((void**)&xh,    g_xh);
    cudaGetSymbolAddress((void**)&xl,    g_xl);
    cudaGetSymbolAddress((void**)&Winh,  g_Winh);
    cudaGetSymbolAddress((void**)&Winl,  g_Winl);
    cudaGetSymbolAddress((void**)&Wxh,   g_Wxh);
    cudaGetSymbolAddress((void**)&Wxl,   g_Wxl);
    cudaGetSymbolAddress((void**)&Wdth,  g_Wdth);
    cudaGetSymbolAddress((void**)&Wdtl,  g_Wdtl);
    cudaGetSymbolAddress((void**)&Wouth, g_Wouth);
    cudaGetSymbolAddress((void**)&Woutl, g_Woutl);
    cudaGetSymbolAddress((void**)&xch,   g_xch);
    cudaGetSymbolAddress((void**)&xcl,   g_xcl);
    cudaGetSymbolAddress((void**)&dbch,  g_dbch);
    cudaGetSymbolAddress((void**)&dbcl,  g_dbcl);
    cudaGetSymbolAddress((void**)&ych,   g_ych);
    cudaGetSymbolAddress((void**)&ycl,   g_ycl);

    // A) one-shot split of x + all weights
    const size_t tot4 = (N_X + N_WIN + 2*N_WX + 2*N_WDT + N_WOUT) / 4;
    split_all<<<(unsigned)((tot4 + 255) / 256), 256>>>(
        x, W_in, Wx0, Wx1, Wdt0, Wdt1, W_out);

    // 0) xz = x @ W_in.T : (2048 x 4096), K=1024
    tgemm_bf16<<<dim3(2 * ED / 128, MROWS / 128, 1), 256, 65536>>>(
        xh, xl, DM, 0, Winh, Winl, Winh, Winl, DM,
        p_xz, 2 * ED, 0, MROWS, 2 * ED, DM, DM, 1, 0, nullptr, nullptr);

    // 1) conv + silu (writes fp32 + bf16 hi/lo), both dirs
    conv_silu_kernel<<<(unsigned)((2 * NED + 255) / 256), 256>>>(
        p_xz, cw0, cb0, cw1, cb1, p_xc);

    // 2) dbc partials = xconv @ Wx.T : (2048 x 96), K=2048, split-K x8, both dirs
    tgemm_bf16<<<dim3(1, MROWS / 128, 2 * SPLITS), 256, 65536>>>(
        xch, xcl, ED, NED, Wxh, Wxl, Wxh + N_WX, Wxl + N_WX, ED,
        p_dbcp, KX, (size_t)SPLITS * NDBC,
        MROWS, KX, ED, ED / SPLITS, SPLITS, 0, nullptr, nullptr);

    // 3) reduce partials (+ bf16 split)
    reduce_splits<<<(unsigned)((2 * NDBC + 255) / 256), 256>>>(
        p_dbcp, p_dbc, (int)NDBC);

    // 4) delta = softplus(dbc[:, :64] @ Wdt.T + b_dt), K=64, both dirs
    tgemm_bf16<<<dim3(ED / 128, MROWS / 128, 2), 256, 65536>>>(
        dbch, dbcl, KX, NDBC, Wdth, Wdtl, Wdth + N_WDT, Wdtl + N_WDT, DTR,
        p_delta, ED, NED, MROWS, ED, DTR, DTR, 1, 1, bdt0, bdt1);

    // 5) selective scan, both dirs
    scan_kernel<<<512, 128>>>(p_delta, p_xc, p_dbc, p_xz,
                              Al0, Al1, Dp0, Dp1, p_y);

    // 6) combine y = 0.5*(y0+y1) -> bf16 hi/lo
    combine_kernel<<<(unsigned)((NED / 4 + 255) / 256), 256>>>(p_y);

    // 7) out = yc @ W_out.T : (2048 x 1024), K=2048
    tgemm_bf16<<<dim3(DM / 128, MROWS / 128, 1), 256, 65536>>>(
        ych, ycl, ED, 0, Wouth, Woutl, Wouth, Woutl, ED,
        out, DM, 0, MROWS, DM, ED, ED, 1, 0, nullptr, nullptr);
}

// round 12
// speedup vs baseline: 2.6437x; 1.0552x over previous
#include <cuda_runtime.h>
#include <cuda_bf16.h>
#include <math.h>

#define B_SZ 4
#define LSEQ 512
#define DM   1024
#define ED   2048
#define NS   16
#define DTR  64
#define KX   96                 // DTR + 2*NS
#define MROWS (B_SZ*LSEQ)       // 2048
#define SPLITS 8
#define NED   ((size_t)MROWS * ED)
#define NDBC  ((size_t)MROWS * KX)
#define NOUT  ((size_t)MROWS * DM)

#define N_X    ((size_t)MROWS * DM)
#define N_WIN  ((size_t)2 * ED * DM)
#define N_WX   ((size_t)KX * ED)
#define N_WDT  ((size_t)ED * DTR)
#define N_WOUT ((size_t)DM * ED)

// ---------------- scratch (static device globals; no runtime allocation) ----
__device__ __align__(16) float g_xz   [(size_t)MROWS * 2 * ED];
__device__ __align__(16) float g_xconv[2 * NED];
__device__ __align__(16) float g_dbc  [2 * NDBC];
__device__ __align__(16) float g_dbcp [2 * (size_t)SPLITS * NDBC];
__device__ __align__(16) float g_delta[2 * NED];   // reused post-scan for out partials
__device__ __align__(16) float g_y    [2 * NED];

// bf16 hi/lo split operands
__device__ __align__(16) __nv_bfloat16 g_xh[N_X],     g_xl[N_X];
__device__ __align__(16) __nv_bfloat16 g_Winh[N_WIN], g_Winl[N_WIN];
__device__ __align__(16) __nv_bfloat16 g_Wxh[2*N_WX], g_Wxl[2*N_WX];
__device__ __align__(16) __nv_bfloat16 g_Wdth[2*N_WDT], g_Wdtl[2*N_WDT];
__device__ __align__(16) __nv_bfloat16 g_Wouth[N_WOUT], g_Woutl[N_WOUT];
__device__ __align__(16) __nv_bfloat16 g_xch[2*NED], g_xcl[2*NED];
__device__ __align__(16) __nv_bfloat16 g_dbch[2*NDBC], g_dbcl[2*NDBC];
__device__ __align__(16) __nv_bfloat16 g_ych[NED], g_ycl[NED];

__device__ __forceinline__ float sigmoidf_(float v) {
    return 1.f / (1.f + __expf(-v));
}

__device__ __forceinline__ void s1(float v, __nv_bfloat16& h, __nv_bfloat16& l) {
    h = __float2bfloat16(v);
    l = __float2bfloat16(v - __bfloat162float(h));
}

// bf16 m16n8k16 MMA (row.col), fp32 accumulate in-place.
__device__ __forceinline__ void mma_bf16(float c[4],
                                         unsigned a0, unsigned a1,
                                         unsigned a2, unsigned a3,
                                         unsigned b0, unsigned b1)
{
    asm volatile(
        "mma.sync.aligned.m16n8k16.row.col.f32.bf16.bf16.f32 "
        "{%0,%1,%2,%3}, {%4,%5,%6,%7}, {%8,%9}, {%0,%1,%2,%3};\n"
        : "+f"(c[0]), "+f"(c[1]), "+f"(c[2]), "+f"(c[3])
        : "r"(a0), "r"(a1), "r"(a2), "r"(a3), "r"(b0), "r"(b1));
}

__device__ __forceinline__ void ldsm_x4(unsigned& r0, unsigned& r1,
                                        unsigned& r2, unsigned& r3, unsigned a)
{
    asm volatile("ldmatrix.sync.aligned.m8n8.x4.shared.b16 {%0,%1,%2,%3}, [%4];"
                 : "=r"(r0), "=r"(r1), "=r"(r2), "=r"(r3) : "r"(a));
}

__device__ __forceinline__ void ldsm_x2(unsigned& r0, unsigned& r1, unsigned a)
{
    asm volatile("ldmatrix.sync.aligned.m8n8.x2.shared.b16 {%0,%1}, [%2];"
                 : "=r"(r0), "=r"(r1) : "r"(a));
}

__device__ __forceinline__ void cpa16(unsigned saddr, const void* g, bool v) {
    asm volatile("cp.async.ca.shared.global [%0], [%1], 16, %2;\n"
                 :: "r"(saddr), "l"(g), "r"(v ? 16 : 0));
}

// ---------------------------------------------------------------------------
// Tensor-core NT GEMM, pre-split bf16 (3-MMA compensated):
//   C[m,n] = sum_k (Ah+Al)[m,k] * (Bh+Bl)[n,k]  (dropping Al*Bl)
// BM=BN=128, BK=32, 256 threads = 8 warps (2x4), warp tile 64x32.
// __launch_bounds__(256,2): cap regs at 128 so 2 CTAs/SM co-reside.
// blockIdx.z = dir*zdiv + split s. epi1 = softplus(v+bias[n]).
// ---------------------------------------------------------------------------
__global__ __launch_bounds__(256, 2) void tgemm_bf16(
    const __nv_bfloat16* __restrict__ Ahp, const __nv_bfloat16* __restrict__ Alp,
    int lda, size_t sAdir,
    const __nv_bfloat16* __restrict__ Bh0, const __nv_bfloat16* __restrict__ Bl0,
    const __nv_bfloat16* __restrict__ Bh1, const __nv_bfloat16* __restrict__ Bl1,
    int ldb,
    float* __restrict__ C, int ldc, size_t sCdir,
    int M, int N, int Ktot, int ksz, int zdiv,
    int epi, const float* __restrict__ bias0, const float* __restrict__ bias1)
{
    extern __shared__ unsigned smem[];   // 2 x 32KB

    const int bm  = blockIdx.y * 128;
    const int bn  = blockIdx.x * 128;
    const int dir = blockIdx.z / zdiv;
    const int s   = blockIdx.z % zdiv;
    const int k0  = s * ksz;
    int k1 = k0 + ksz; if (k1 > Ktot) k1 = Ktot;
    const int T = (k1 - k0) >> 5;        // BK=32 tiles

    const __nv_bfloat16* Ah = Ahp + (size_t)dir * sAdir;
    const __nv_bfloat16* Al = Alp + (size_t)dir * sAdir;
    const __nv_bfloat16* Bh = dir ? Bh1 : Bh0;
    const __nv_bfloat16* Bl = dir ? Bl1 : Bl0;
    const float* bias = dir ? bias1 : bias0;
    float* Cout = C + (size_t)dir * sCdir + (size_t)s * (size_t)M * (size_t)ldc;

    const int tid  = threadIdx.x;
    const int warp = tid >> 5, lane = tid & 31;
    const int wm = (warp >> 2) * 64;
    const int wn = (warp & 3) * 32;
    const int qr = lane >> 2;            // 0..7
    const int qc = lane & 3;             // 0..3

    unsigned sbase = (unsigned)__cvta_generic_to_shared(smem);

    auto stage = [&](int kbase, int buf) {
        unsigned base = sbase + buf * 32768;
#pragma unroll
        for (int u = tid; u < 512; u += 256) {
            int row = u >> 2, grp = u & 3;
            int gp = grp ^ ((row >> 1) & 3);
            unsigned so = base + (unsigned)(row * 64 + gp * 16);
            const size_t ka = (size_t)(bm + row) * lda + kbase + grp * 8;
            cpa16(so,          Ah + ka, true);
            cpa16(so +  8192,  Al + ka, true);
            bool bv = (bn + row) < N;
            const size_t kb = (size_t)(bn + row) * ldb + kbase + grp * 8;
            cpa16(so + 16384,  Bh + kb, bv);
            cpa16(so + 24576,  Bl + kb, bv);
        }
        asm volatile("cp.async.commit_group;\n");
    };

    // precomputed ldmatrix byte offsets (within one operand array, kk=0)
    unsigned aoff[4], boff[4];
#pragma unroll
    for (int i = 0; i < 4; i++) {
        int row = wm + i * 16 + (lane & 15);
        int ch  = lane >> 4;                      // 0: k0-7, 1: k8-15
        int g   = ch ^ ((row >> 1) & 3);
        aoff[i] = (unsigned)(row * 64 + g * 16);
    }
#pragma unroll
    for (int j = 0; j < 4; j++) {
        int row = wn + j * 8 + (lane & 7);
        int ch  = (lane >> 3) & 1;
        int g   = ch ^ ((row >> 1) & 3);
        boff[j] = (unsigned)(row * 64 + g * 16);
    }

    float acc[4][4][4];
#pragma unroll
    for (int i = 0; i < 4; i++)
#pragma unroll
        for (int j = 0; j < 4; j++)
#pragma unroll
            for (int r = 0; r < 4; r++) acc[i][j][r] = 0.f;

    stage(k0, 0);

    for (int t = 0; t < T; t++) {
        const int nxt = (t + 1 < T) ? t + 1 : t;
        stage(k0 + nxt * 32, (t + 1) & 1);
        asm volatile("cp.async.wait_group 1;\n");
        __syncthreads();

        const unsigned Ab = sbase + (t & 1) * 32768;

#pragma unroll
        for (int kk = 0; kk < 2; kk++) {
            const unsigned kx = kk * 32;          // chunk 0/1 -> 2/3 via XOR
            unsigned bh0[4], bh1[4], bl0[4], bl1[4];
#pragma unroll
            for (int j = 0; j < 4; j++) {
                ldsm_x2(bh0[j], bh1[j], Ab + 16384 + (boff[j] ^ kx));
                ldsm_x2(bl0[j], bl1[j], Ab + 24576 + (boff[j] ^ kx));
            }
#pragma unroll
            for (int i = 0; i < 4; i++) {
                unsigned ah0, ah1, ah2, ah3, al0, al1, al2, al3;
                ldsm_x4(ah0, ah1, ah2, ah3, Ab + (aoff[i] ^ kx));
                ldsm_x4(al0, al1, al2, al3, Ab + 8192 + (aoff[i] ^ kx));
#pragma unroll
                for (int j = 0; j < 4; j++) {
                    mma_bf16(acc[i][j], ah0, ah1, ah2, ah3, bh0[j], bh1[j]);
                    mma_bf16(acc[i][j], al0, al1, al2, al3, bh0[j], bh1[j]);
                    mma_bf16(acc[i][j], ah0, ah1, ah2, ah3, bl0[j], bl1[j]);
                }
            }
        }
        __syncthreads();
    }

    // epilogue: (c0,c1)=(qr,2qc..2qc+1), (c2,c3)=(qr+8,..) -> float2 stores
#pragma unroll
    for (int i = 0; i < 4; i++) {
        const int row0 = bm + wm + i * 16 + qr;
#pragma unroll
        for (int j = 0; j < 4; j++) {
            const int cc = bn + wn + j * 8 + qc * 2;
            if (cc < N) {
#pragma unroll
                for (int half = 0; half < 2; half++) {
                    const int rr = row0 + half * 8;
                    float v0 = acc[i][j][half * 2];
                    float v1 = acc[i][j][half * 2 + 1];
                    if (epi == 1) {
                        v0 += bias[cc];
                        v1 += bias[cc + 1];
                        v0 = (v0 > 15.f) ? v0 : __logf(1.f + __expf(v0));
                        v1 = (v1 > 15.f) ? v1 : __logf(1.f + __expf(v1));
                    }
                    *reinterpret_cast<float2*>(&Cout[(size_t)rr * ldc + cc]) =
                        make_float2(v0, v1);
                }
            }
        }
    }
}

// ---------------------------------------------------------------------------
// One-shot split of x + all weights into bf16 hi/lo. 4 elems per thread.
// ---------------------------------------------------------------------------
__global__ __launch_bounds__(256) void split_all(
    const float* __restrict__ x,   const float* __restrict__ Win,
    const float* __restrict__ Wx0, const float* __restrict__ Wx1,
    const float* __restrict__ Wdt0,const float* __restrict__ Wdt1,
    const float* __restrict__ Wout)
{
    const size_t O0 = 0;
    const size_t O1 = O0 + N_X;
    const size_t O2 = O1 + N_WIN;
    const size_t O3 = O2 + N_WX;
    const size_t O4 = O3 + N_WX;
    const size_t O5 = O4 + N_WDT;
    const size_t O6 = O5 + N_WDT;
    const size_t O7 = O6 + N_WOUT;

    size_t i = ((size_t)blockIdx.x * 256 + threadIdx.x) * 4;
    if (i >= O7) return;

    const float* src; __nv_bfloat16 *ph, *pl; size_t off;
    if      (i < O1) { src = x;    ph = g_xh;            pl = g_xl;            off = O0; }
    else if (i < O2) { src = Win;  ph = g_Winh;          pl = g_Winl;          off = O1; }
    else if (i < O3) { src = Wx0;  ph = g_Wxh;           pl = g_Wxl;           off = O2; }
    else if (i < O4) { src = Wx1;  ph = g_Wxh + N_WX;    pl = g_Wxl + N_WX;    off = O3; }
    else if (i < O5) { src = Wdt0; ph = g_Wdth;          pl = g_Wdtl;          off = O4; }
    else if (i < O6) { src = Wdt1; ph = g_Wdth + N_WDT;  pl = g_Wdtl + N_WDT;  off = O5; }
    else             { src = Wout; ph = g_Wouth;         pl = g_Woutl;         off = O6; }

    size_t k = i - off;
    float4 v = *reinterpret_cast<const float4*>(src + k);
    __nv_bfloat16 h[4], l[4];
    s1(v.x, h[0], l[0]); s1(v.y, h[1], l[1]);
    s1(v.z, h[2], l[2]); s1(v.w, h[3], l[3]);
    *reinterpret_cast<uint2*>(ph + k) = *reinterpret_cast<uint2*>(h);
    *reinterpret_cast<uint2*>(pl + k) = *reinterpret_cast<uint2*>(l);
}

// ---------------------------------------------------------------------------
// Reduce split-K partials for both dirs + bf16 split of result.
// ---------------------------------------------------------------------------
__global__ void reduce_splits(const float* __restrict__ part,
                              float* __restrict__ outp, int n1)
{
    int i = blockIdx.x * blockDim.x + threadIdx.x;
    if (i >= 2 * n1) return;
    int dir = i / n1, ii = i - dir * n1;
    const float* p = part + (size_t)dir * SPLITS * n1;
    float s = 0.f;
#pragma unroll
    for (int j = 0; j < SPLITS; j++) s += p[(size_t)j * n1 + ii];
    outp[i] = s;
    s1(s, g_dbch[i], g_dbcl[i]);
}

// ---------------------------------------------------------------------------
// Sum the 2 out-GEMM split-K partials (vectorized float4).
// ---------------------------------------------------------------------------
__global__ void reduce_out(const float* __restrict__ part,
                           float* __restrict__ outp)
{
    size_t i = ((size_t)blockIdx.x * 256 + threadIdx.x) * 4;
    if (i >= NOUT) return;
    float4 a = *reinterpret_cast<const float4*>(part + i);
    float4 b = *reinterpret_cast<const float4*>(part + NOUT + i);
    *reinterpret_cast<float4*>(outp + i) =
        make_float4(a.x + b.x, a.y + b.y, a.z + b.z, a.w + b.w);
}

// ---------------------------------------------------------------------------
// Causal depthwise conv (K=4) + SiLU, both dirs; writes fp32 + bf16 hi/lo.
// ---------------------------------------------------------------------------
__global__ __launch_bounds__(256) void conv_silu_kernel(
    const float* __restrict__ xz,
    const float* __restrict__ w0, const float* __restrict__ cb0,
    const float* __restrict__ w1, const float* __restrict__ cb1,
    float* __restrict__ xc)
{
    size_t idx = (size_t)blockIdx.x * blockDim.x + threadIdx.x;
    if (idx >= 2 * NED) return;
    const int dir = (int)(idx / NED);
    size_t loc = idx - (size_t)dir * NED;
    int e = (int)(loc % ED);
    int t = (int)((loc / ED) % LSEQ);
    int b = (int)(loc / ((size_t)ED * LSEQ));
    const float* w  = dir ? w1  : w0;
    const float* cb = dir ? cb1 : cb0;

    float acc = cb[e];
#pragma unroll
    for (int i = 0; i < 4; i++) {
        int tau = t - 3 + i;
        if (tau >= 0) {
            int tt = dir ? (LSEQ - 1 - tau) : tau;
            acc = fmaf(w[e * 4 + i],
                       xz[((size_t)b * LSEQ + tt) * (2 * ED) + e], acc);
        }
    }
    float val = acc * sigmoidf_(acc);
    xc[idx] = val;
    s1(val, g_xch[idx], g_xcl[idx]);
}

// ---------------------------------------------------------------------------
// Combine y = 0.5*(y0+y1) and split to bf16 hi/lo for the output GEMM.
// ---------------------------------------------------------------------------
__global__ __launch_bounds__(256) void combine_kernel(
    const float* __restrict__ y)
{
    size_t i = ((size_t)blockIdx.x * 256 + threadIdx.x) * 4;
    if (i >= NED) return;
    float4 a = *reinterpret_cast<const float4*>(y + i);
    float4 b = *reinterpret_cast<const float4*>(y + NED + i);
    __nv_bfloat16 h[4], l[4];
    s1(0.5f * (a.x + b.x), h[0], l[0]);
    s1(0.5f * (a.y + b.y), h[1], l[1]);
    s1(0.5f * (a.z + b.z), h[2], l[2]);
    s1(0.5f * (a.w + b.w), h[3], l[3]);
    *reinterpret_cast<uint2*>(g_ych + i) = *reinterpret_cast<uint2*>(h);
    *reinterpret_cast<uint2*>(g_ycl + i) = *reinterpret_cast<uint2*>(l);
}

// ---------------------------------------------------------------------------
// Selective scan, both directions in one launch (512 blocks x 128 threads).
// ---------------------------------------------------------------------------
__global__ __launch_bounds__(128) void scan_kernel(
    const float* __restrict__ delta,
    const float* __restrict__ xconv,
    const float* __restrict__ dbc,
    const float* __restrict__ xz,
    const float* __restrict__ A0, const float* __restrict__ A1,
    const float* __restrict__ D0, const float* __restrict__ D1,
    float* __restrict__ y)
{
    const int dir = blockIdx.x >> 8;
    const int rb  = blockIdx.x & 255;
    const int b   = rb >> 6;
    const int ec  = rb & 63;
    const int tid = threadIdx.x;
    const int e = ec * 32 + (tid >> 2);
    const int g = tid & 3;

    const float* dlt  = delta + (size_t)dir * NED;
    const float* xcv  = xconv + (size_t)dir * NED;
    const float* dbcd = dbc + (size_t)dir * NDBC;
    const float* A_log = dir ? A1 : A0;
    const float* Dp    = dir ? D1 : D0;
    float* yo = y + (size_t)dir * NED;

    float4 al = *reinterpret_cast<const float4*>(&A_log[e * NS + g * 4]);
    const float Aa = -__expf(al.x), Ab = -__expf(al.y),
                Ac = -__expf(al.z), Ad = -__expf(al.w);
    const float dp = Dp[e];

    float h0 = 0.f, h1 = 0.f, h2 = 0.f, h3 = 0.f;
    const size_t baseBL = (size_t)b * LSEQ;

    for (int t = 0; t < LSEQ; t++) {
        const size_t row = baseBL + t;
        const float d  = dlt[row * ED + e];
        const float xv = xcv[row * ED + e];
        const int   tt = dir ? (LSEQ - 1 - t) : t;
        const float zv = xz[(baseBL + tt) * (2 * ED) + ED + e];
        float4 Bv = *reinterpret_cast<const float4*>(&dbcd[row * KX + DTR + g * 4]);
        float4 Cv = *reinterpret_cast<const float4*>(&dbcd[row * KX + DTR + NS + g * 4]);

        const float dx = d * xv;
        h0 = fmaf(__expf(d * Aa), h0, dx * Bv.x);
        h1 = fmaf(__expf(d * Ab), h1, dx * Bv.y);
        h2 = fmaf(__expf(d * Ac), h2, dx * Bv.z);
        h3 = fmaf(__expf(d * Ad), h3, dx * Bv.w);

        float yp = h0 * Cv.x + h1 * Cv.y + h2 * Cv.z + h3 * Cv.w;
        yp += __shfl_xor_sync(0xffffffffu, yp, 1);
        yp += __shfl_xor_sync(0xffffffffu, yp, 2);

        if (g == 0) {
            float yt  = yp + dp * xv;
            float val = yt * (zv * sigmoidf_(zv));
            size_t orow = dir ? (baseBL + (LSEQ - 1 - t)) : row;
            yo[orow * ED + e] = val;
        }
    }
}

// ---------------------------------------------------------------------------
extern "C" void kernel_launch(void* const* d_in, const int* in_sizes, int n_in,
                              void* d_out, int out_size)
{
    (void)in_sizes; (void)n_in; (void)out_size;
    const float* x     = (const float*)d_in[0];
    const float* W_in  = (const float*)d_in[1];
    const float* cw0   = (const float*)d_in[2];
    const float* cb0   = (const float*)d_in[3];
    const float* Wx0   = (const float*)d_in[4];
    const float* Wdt0  = (const float*)d_in[5];
    const float* bdt0  = (const float*)d_in[6];
    const float* Al0   = (const float*)d_in[7];
    const float* Dp0   = (const float*)d_in[8];
    const float* cw1   = (const float*)d_in[9];
    const float* cb1   = (const float*)d_in[10];
    const float* Wx1   = (const float*)d_in[11];
    const float* Wdt1  = (const float*)d_in[12];
    const float* bdt1  = (const float*)d_in[13];
    const float* Al1   = (const float*)d_in[14];
    const float* Dp1   = (const float*)d_in[15];
    const float* W_out = (const float*)d_in[16];
    float* out = (float*)d_out;

    cudaFuncSetAttribute(tgemm_bf16,
                         cudaFuncAttributeMaxDynamicSharedMemorySize, 65536);

    float *p_xz, *p_xc, *p_dbc, *p_dbcp, *p_delta, *p_y;
    cudaGetSymbolAddress((void**)&p_xz,    g_xz);
    cudaGetSymbolAddress((void**)&p_xc,    g_xconv);
    cudaGetSymbolAddress((void**)&p_dbc,   g_dbc);
    cudaGetSymbolAddress((void**)&p_dbcp,  g_dbcp);
    cudaGetSymbolAddress((void**)&p_delta, g_delta);
    cudaGetSymbolAddress((void**)&p_y,     g_y);

    __nv_bfloat16 *xh, *xl, *Winh, *Winl, *Wxh, *Wxl, *Wdth, *Wdtl;
    __nv_bfloat16 *Wouth, *Woutl, *xch, *xcl, *dbch, *dbcl, *ych, *ycl;
    cudaGetSymbolAddress((void**)&xh,    g_xh);
    cudaGetSymbolAddress((void**)&xl,    g_xl);
    cudaGetSymbolAddress((void**)&Winh,  g_Winh);
    cudaGetSymbolAddress((void**)&Winl,  g_Winl);
    cudaGetSymbolAddress((void**)&Wxh,   g_Wxh);
    cudaGetSymbolAddress((void**)&Wxl,   g_Wxl);
    cudaGetSymbolAddress((void**)&Wdth,  g_Wdth);
    cudaGetSymbolAddress((void**)&Wdtl,  g_Wdtl);
    cudaGetSymbolAddress((void**)&Wouth, g_Wouth);
    cudaGetSymbolAddress((void**)&Woutl, g_Woutl);
    cudaGetSymbolAddress((void**)&xch,   g_xch);
    cudaGetSymbolAddress((void**)&xcl,   g_xcl);
    cudaGetSymbolAddress((void**)&dbch,  g_dbch);
    cudaGetSymbolAddress((void**)&dbcl,  g_dbcl);
    cudaGetSymbolAddress((void**)&ych,   g_ych);
    cudaGetSymbolAddress((void**)&ycl,   g_ycl);

    // A) one-shot split of x + all weights
    const size_t tot4 = (N_X + N_WIN + 2*N_WX + 2*N_WDT + N_WOUT) / 4;
    split_all<<<(unsigned)((tot4 + 255) / 256), 256>>>(
        x, W_in, Wx0, Wx1, Wdt0, Wdt1, W_out);

    // 0) xz = x @ W_in.T : (2048 x 4096), K=1024
    tgemm_bf16<<<dim3(2 * ED / 128, MROWS / 128, 1), 256, 65536>>>(
        xh, xl, DM, 0, Winh, Winl, Winh, Winl, DM,
        p_xz, 2 * ED, 0, MROWS, 2 * ED, DM, DM, 1, 0, nullptr, nullptr);

    // 1) conv + silu (writes fp32 + bf16 hi/lo), both dirs
    conv_silu_kernel<<<(unsigned)((2 * NED + 255) / 256), 256>>>(
        p_xz, cw0, cb0, cw1, cb1, p_xc);

    // 2) dbc partials = xconv @ Wx.T : (2048 x 96), K=2048, split-K x8, both dirs
    tgemm_bf16<<<dim3(1, MROWS / 128, 2 * SPLITS), 256, 65536>>>(
        xch, xcl, ED, NED, Wxh, Wxl, Wxh + N_WX, Wxl + N_WX, ED,
        p_dbcp, KX, (size_t)SPLITS * NDBC,
        MROWS, KX, ED, ED / SPLITS, SPLITS, 0, nullptr, nullptr);

    // 3) reduce partials (+ bf16 split)
    reduce_splits<<<(unsigned)((2 * NDBC + 255) / 256), 256>>>(
        p_dbcp, p_dbc, (int)NDBC);

    // 4) delta = softplus(dbc[:, :64] @ Wdt.T + b_dt), K=64, both dirs
    tgemm_bf16<<<dim3(ED / 128, MROWS / 128, 2), 256, 65536>>>(
        dbch, dbcl, KX, NDBC, Wdth, Wdtl, Wdth + N_WDT, Wdtl + N_WDT, DTR,
        p_delta, ED, NED, MROWS, ED, DTR, DTR, 1, 1, bdt0, bdt1);

    // 5) selective scan, both dirs
    scan_kernel<<<512, 128>>>(p_delta, p_xc, p_dbc, p_xz,
                              Al0, Al1, Dp0, Dp1, p_y);

    // 6) combine y = 0.5*(y0+y1) -> bf16 hi/lo
    combine_kernel<<<(unsigned)((NED / 4 + 255) / 256), 256>>>(p_y);

    // 7) out partials = yc @ W_out.T : (2048 x 1024), K=2048, split-K x2
    //    (delta buffer is dead after the scan; reuse it for partials)
    tgemm_bf16<<<dim3(DM / 128, MROWS / 128, 2), 256, 65536>>>(
        ych, ycl, ED, 0, Wouth, Woutl, Wouth, Woutl, ED,
        p_delta, DM, 0, MROWS, DM, ED, ED / 2, 2, 0, nullptr, nullptr);

    // 8) out = partial0 + partial1
    reduce_out<<<(unsigned)((NOUT / 4 + 255) / 256), 256>>>(p_delta, out);
}